// round 6
// baseline (speedup 1.0000x reference)
#include <cuda_runtime.h>

#define NN 50000
#define NN2 50176          // 784*64 padded rows (pad stays zero)
#define EE 800000
#define INF 128
#define NB 32
#define H_OFF 65536        // h starts after adj (256*256)
#define OUT_ELEMS 98304    // 256*256 + 256*128
#define WELEMS 98304       // 384*256 weight elements

__device__ __forceinline__ int graph_of(int n) { return (n * NB) / NN; }

// ---- scratch (module globals; zero-initialized, no runtime allocation) ----
__device__ float g_r[NN * 8];
__device__ int   g_counts[53248];              // padded for unguarded int4 scan reads
__device__ int   g_off[NN + 1];
__device__ int   g_cursor[NN];
__device__ int2  g_sorted[EE];
__device__ unsigned int g_A32[(size_t)NN2 * 256];  // tf32 [x | neigh]; pad rows stay 0
__device__ unsigned int g_BT[384 * 256];           // tf32 W^T: [n][k]

// ================= helpers =================
__device__ __forceinline__ unsigned int smem_u32(const void* p) {
    unsigned int a;
    asm("{ .reg .u64 t; cvta.to.shared.u64 t, %1; cvt.u32.u64 %0, t; }" : "=r"(a) : "l"(p));
    return a;
}
__device__ __forceinline__ unsigned int f2tf32(float v) {
    unsigned int o;
    asm("cvt.rna.tf32.f32 %0, %1;" : "=r"(o) : "f"(v));
    return o;
}
#define CP_ASYNC16(dst, src) \
    asm volatile("cp.async.ca.shared.global [%0], [%1], 16;" :: "r"(dst), "l"(src) : "memory")
#define CP_COMMIT()  asm volatile("cp.async.commit_group;" ::: "memory")
#define CP_WAIT1()   asm volatile("cp.async.wait_group 1;" ::: "memory")
#define CP_WAIT0()   asm volatile("cp.async.wait_group 0;" ::: "memory")

__device__ __forceinline__ void mma16n8k8(float* d, const unsigned* a, const unsigned* b) {
    asm volatile(
        "mma.sync.aligned.m16n8k8.row.col.f32.tf32.tf32.f32 "
        "{%0,%1,%2,%3}, {%4,%5,%6,%7}, {%8,%9}, {%0,%1,%2,%3};"
        : "+f"(d[0]), "+f"(d[1]), "+f"(d[2]), "+f"(d[3])
        : "r"(a[0]), "r"(a[1]), "r"(a[2]), "r"(a[3]), "r"(b[0]), "r"(b[1]));
}

// ---------------------------------------------------------------- init: zero counts+out, convert W
__global__ void k_init(float* __restrict__ out,
                       const float* __restrict__ We, const float* __restrict__ Wp) {
    int i = blockIdx.x * blockDim.x + threadIdx.x;
    const int total = NN + OUT_ELEMS + WELEMS;
    for (; i < total; i += gridDim.x * blockDim.x) {
        if (i < NN) g_counts[i] = 0;
        else if (i < NN + OUT_ELEMS) out[i - NN] = 0.0f;
        else {
            int idx = i - NN - OUT_ELEMS;       // 0..98303
            int k = idx & 255, n = idx >> 8;
            float v = (n < 128) ? We[k * 128 + n] : Wp[k * 256 + (n - 128)];
            g_BT[n * 256 + k] = f2tf32(v);
        }
    }
}

// ---------------------------------------------------------------- prep X: tf32 image (cols 0..127)
__global__ void k_prepX(const float* __restrict__ x) {
    int i = blockIdx.x * 256 + threadIdx.x;
    if (i < NN * INF) {
        int row = i >> 7, col = i & 127;
        g_A32[(size_t)row * 256 + col] = f2tf32(x[i]);
    }
}

// ---------------------------------------------------------------- histogram of dst
__global__ void k_hist(const int* __restrict__ ei) {
    int e = blockIdx.x * 256 + threadIdx.x;
    if (e < EE) atomicAdd(&g_counts[ei[EE + e]], 1);
}

// ---------------------------------------------------------------- exclusive scan (1 block, int4)
__global__ void k_scan() {
    const int CH = 52;  // 1024*52 = 53248; counts padded & zero beyond NN
    int t = threadIdx.x, lane = t & 31, wid = t >> 5;
    int base = t * CH;
    int s = 0;
    const int4* cp4 = reinterpret_cast<const int4*>(g_counts + base);
    int4 v4[13];
    #pragma unroll
    for (int i = 0; i < 13; i++) v4[i] = cp4[i];
    #pragma unroll
    for (int i = 0; i < 13; i++) s += v4[i].x + v4[i].y + v4[i].z + v4[i].w;
    int orig = s;
    #pragma unroll
    for (int o = 1; o < 32; o <<= 1) {
        int v = __shfl_up_sync(0xFFFFFFFFu, s, o);
        if (lane >= o) s += v;
    }
    __shared__ int ws[32];
    if (lane == 31) ws[wid] = s;
    __syncthreads();
    if (wid == 0) {
        int v = ws[lane];
        #pragma unroll
        for (int o = 1; o < 32; o <<= 1) {
            int u = __shfl_up_sync(0xFFFFFFFFu, v, o);
            if (lane >= o) v += u;
        }
        ws[lane] = v;
    }
    __syncthreads();
    int run = s - orig + (wid ? ws[wid - 1] : 0);
    #pragma unroll
    for (int i = 0; i < 13; i++) {
        int c[4] = {v4[i].x, v4[i].y, v4[i].z, v4[i].w};
        #pragma unroll
        for (int j = 0; j < 4; j++) {
            int idx = base + i * 4 + j;
            if (idx < NN) { g_off[idx] = run; g_cursor[idx] = run; }
            run += c[j];
        }
    }
    if (t == 0) g_off[NN] = EE;
}

// ---------------------------------------------------------------- scatter into dst-sorted order
__global__ void k_scatter(const int* __restrict__ ei) {
    int e = blockIdx.x * 256 + threadIdx.x;
    if (e < EE) {
        int s = ei[e], d = ei[EE + e];
        int pos = atomicAdd(&g_cursor[d], 1);
        g_sorted[pos] = make_int2(s, d);
    }
}

// ---------------------------------------------------------------- mean aggregation -> tf32 cols 128..255
__global__ void k_neigh(const float* __restrict__ x) {
    int node = blockIdx.x * 8 + (threadIdx.x >> 5);
    if (node >= NN) return;
    int lane = threadIdx.x & 31;
    int b = g_off[node], e = g_off[node + 1];
    float4 a0 = make_float4(0.f, 0.f, 0.f, 0.f);
    float4 a1 = make_float4(0.f, 0.f, 0.f, 0.f);
    int j = b;
    for (; j + 1 < e; j += 2) {
        int s0 = g_sorted[j].x, s1 = g_sorted[j + 1].x;
        float4 v0 = *reinterpret_cast<const float4*>(x + (size_t)s0 * INF + lane * 4);
        float4 v1 = *reinterpret_cast<const float4*>(x + (size_t)s1 * INF + lane * 4);
        a0.x += v0.x; a0.y += v0.y; a0.z += v0.z; a0.w += v0.w;
        a1.x += v1.x; a1.y += v1.y; a1.z += v1.z; a1.w += v1.w;
    }
    if (j < e) {
        int s0 = g_sorted[j].x;
        float4 v0 = *reinterpret_cast<const float4*>(x + (size_t)s0 * INF + lane * 4);
        a0.x += v0.x; a0.y += v0.y; a0.z += v0.z; a0.w += v0.w;
    }
    float inv = 1.0f / (float)max(e - b, 1);
    uint4 tv;
    tv.x = f2tf32((a0.x + a1.x) * inv); tv.y = f2tf32((a0.y + a1.y) * inv);
    tv.z = f2tf32((a0.z + a1.z) * inv); tv.w = f2tf32((a0.w + a1.w) * inv);
    *reinterpret_cast<uint4*>(g_A32 + (size_t)node * 256 + 128 + lane * 4) = tv;
}

// ---------------------------------------------------------------- fused GEMM(64x384) + softmax + r + h
// SMEM words: Abuf[2] @ 0,2048 (64x32 sw); Bbuf[2] @ 4096,16384 (384x32 sw).
// Epilogue reuse: Zs @ 0 (64 x 388), hacc @ 24832 (2*8*128). Total 28672 words.
#define FS_WORDS 28672
#define ZLD 388
__global__ __launch_bounds__(256, 1) void k_fused(const float* __restrict__ be,
                                                  const float* __restrict__ bp,
                                                  float* __restrict__ out) {
    extern __shared__ unsigned int sm[];
    __shared__ float bias_s[384];
    int tid = threadIdx.x, lane = tid & 31, wid = tid >> 5;
    int warp_m = wid >> 2, warp_n = wid & 3;       // 2 x 4 warps
    int g = lane >> 2, t = lane & 3;
    int m0 = blockIdx.x * 64;
    unsigned int sbase = smem_u32(sm);

    if (tid < 128) bias_s[tid] = be[tid];
    bias_s[128 + tid] = bp[tid];

    float acc[2][12][4];
    #pragma unroll
    for (int mt = 0; mt < 2; mt++)
        #pragma unroll
        for (int nt = 0; nt < 12; nt++)
            #pragma unroll
            for (int j = 0; j < 4; j++) acc[mt][nt][j] = 0.0f;

    auto load_chunk = [&](int c, int buf) {
        int k0 = c * 32;
        unsigned int sa = sbase + (buf * 2048) * 4;
        unsigned int sb = sbase + (4096 + buf * 12288) * 4;
        #pragma unroll
        for (int i = 0; i < 2; i++) {
            int e = tid + i * 256;                 // 0..511
            int m = e >> 3, ch = e & 7;
            CP_ASYNC16(sa + (m * 32 + ((ch ^ (m & 7)) << 2)) * 4,
                       g_A32 + (size_t)(m0 + m) * 256 + k0 + ch * 4);
        }
        #pragma unroll
        for (int i = 0; i < 12; i++) {
            int e = tid + i * 256;                 // 0..3071
            int n = e >> 3, ch = e & 7;
            CP_ASYNC16(sb + (n * 32 + ((ch ^ (n & 7)) << 2)) * 4,
                       g_BT + (size_t)n * 256 + k0 + ch * 4);
        }
    };
    auto compute = [&](int buf) {
        const unsigned int* As = sm + buf * 2048;
        const unsigned int* Bs = sm + 4096 + buf * 12288;
        #pragma unroll
        for (int ks = 0; ks < 4; ks++) {
            unsigned int a[2][4], b[12][2];
            int c0 = 2 * ks, c1 = 2 * ks + 1;
            #pragma unroll
            for (int mt = 0; mt < 2; mt++) {
                int r0 = warp_m * 32 + mt * 16 + g;   // r0&7 == g
                int r1 = r0 + 8;
                a[mt][0] = As[r0 * 32 + ((c0 ^ g) << 2) + t];
                a[mt][1] = As[r1 * 32 + ((c0 ^ g) << 2) + t];
                a[mt][2] = As[r0 * 32 + ((c1 ^ g) << 2) + t];
                a[mt][3] = As[r1 * 32 + ((c1 ^ g) << 2) + t];
            }
            #pragma unroll
            for (int nt = 0; nt < 12; nt++) {
                int n = warp_n * 96 + nt * 8 + g;     // n&7 == g
                b[nt][0] = Bs[n * 32 + ((c0 ^ g) << 2) + t];
                b[nt][1] = Bs[n * 32 + ((c1 ^ g) << 2) + t];
            }
            #pragma unroll
            for (int mt = 0; mt < 2; mt++)
                #pragma unroll
                for (int nt = 0; nt < 12; nt++)
                    mma16n8k8(acc[mt][nt], a[mt], b[nt]);
        }
    };

    load_chunk(0, 0); CP_COMMIT();
    load_chunk(1, 1); CP_COMMIT();
    #pragma unroll
    for (int c = 0; c < 8; c++) {
        if (c < 7) { CP_WAIT1(); } else { CP_WAIT0(); }
        __syncthreads();
        compute(c & 1);
        __syncthreads();
        if (c + 2 < 8) { load_chunk(c + 2, c & 1); CP_COMMIT(); }
    }

    // ---- epilogue: stage Z(+bias) in SMEM, zero hacc ----
    float* Zs = reinterpret_cast<float*>(sm);
    float* hacc = reinterpret_cast<float*>(sm) + 24832;   // [2][8][128]
    __syncthreads();     // all compute done; SMEM reuse safe
    #pragma unroll
    for (int mt = 0; mt < 2; mt++) {
        int r0 = warp_m * 32 + mt * 16 + g;
        #pragma unroll
        for (int nt = 0; nt < 12; nt++) {
            int col = warp_n * 96 + nt * 8 + 2 * t;
            float bx = bias_s[col], by = bias_s[col + 1];
            Zs[r0 * ZLD + col]           = acc[mt][nt][0] + bx;
            Zs[r0 * ZLD + col + 1]       = acc[mt][nt][1] + by;
            Zs[(r0 + 8) * ZLD + col]     = acc[mt][nt][2] + bx;
            Zs[(r0 + 8) * ZLD + col + 1] = acc[mt][nt][3] + by;
        }
    }
    for (int i = tid; i < 2048; i += 256) hacc[i] = 0.0f;
    __syncthreads();

    // ---- softmax + r + h: warp w handles rows w*8 .. w*8+7 ----
    int g0 = graph_of(m0);
    for (int it = 0; it < 8; it++) {
        int rloc = wid * 8 + it;
        int n = m0 + rloc;
        if (n >= NN) break;
        const float* zr = Zs + rloc * ZLD;
        float l[8];
        float4 q0 = *reinterpret_cast<const float4*>(zr + 128 + lane * 8);
        float4 q1 = *reinterpret_cast<const float4*>(zr + 128 + lane * 8 + 4);
        l[0] = q0.x; l[1] = q0.y; l[2] = q0.z; l[3] = q0.w;
        l[4] = q1.x; l[5] = q1.y; l[6] = q1.z; l[7] = q1.w;
        float mx = l[0];
        #pragma unroll
        for (int j = 1; j < 8; j++) mx = fmaxf(mx, l[j]);
        #pragma unroll
        for (int o = 16; o > 0; o >>= 1) mx = fmaxf(mx, __shfl_xor_sync(0xFFFFFFFFu, mx, o));
        float ex[8], s = 0.0f;
        #pragma unroll
        for (int j = 0; j < 8; j++) { ex[j] = expf(l[j] - mx); s += ex[j]; }
        #pragma unroll
        for (int o = 16; o > 0; o >>= 1) s += __shfl_xor_sync(0xFFFFFFFFu, s, o);
        float inv_s = 1.0f / s;
        float p[8], pm = -1e30f;
        #pragma unroll
        for (int j = 0; j < 8; j++) { p[j] = ex[j] * inv_s; pm = fmaxf(pm, p[j]); }
        float e2[8], se2 = 0.0f;
        #pragma unroll
        for (int j = 0; j < 8; j++) { e2[j] = expf(p[j] - pm); se2 += e2[j]; }
        float Zf = se2 + 248.0f * expf(-pm);
        float invZ = 1.0f / Zf;
        float invd = 1.0f / (se2 * invZ + 1e-13f);
        float r[8];
        #pragma unroll
        for (int j = 0; j < 8; j++) r[j] = e2[j] * invZ * invd;

        int gn = graph_of(n);
        if (lane == gn) {
            #pragma unroll
            for (int j = 0; j < 8; j++) g_r[n * 8 + j] = r[j];
        }
        float rb[8];
        #pragma unroll
        for (int j = 0; j < 8; j++) rb[j] = __shfl_sync(0xFFFFFFFFu, r[j], gn);

        float4 ev = *reinterpret_cast<const float4*>(zr + lane * 4);
        float* hb = hacc + (gn - g0) * 1024 + lane * 4;
        #pragma unroll
        for (int a = 0; a < 8; a++) {
            float ra = rb[a];
            atomicAdd(hb + a * 128 + 0, ra * ev.x);
            atomicAdd(hb + a * 128 + 1, ra * ev.y);
            atomicAdd(hb + a * 128 + 2, ra * ev.z);
            atomicAdd(hb + a * 128 + 3, ra * ev.w);
        }
    }
    __syncthreads();
    // ---- flush h ----
    for (int i = tid; i < 2048; i += 256) {
        float s = hacc[i];
        int slot = i >> 10, rest = i & 1023, a = rest >> 7, c2 = rest & 127;
        int gg = g0 + slot;
        if (gg < NB && s != 0.0f)
            atomicAdd(out + H_OFF + ((gg << 3) + a) * 128 + c2, s);
    }
}

// ---------------------------------------------------------------- per-edge adj: 8x8 outer products
__global__ __launch_bounds__(256) void k_adj(float* __restrict__ out) {
    __shared__ float acc[2 * 2048];
    int tid = threadIdx.x;
    for (int i = tid; i < 4096; i += 256) acc[i] = 0.0f;
    __syncthreads();
    int e0 = blockIdx.x * 2048;
    int g0 = graph_of(g_sorted[e0].y);
    int warp = tid >> 5, lane = tid & 31;
    int aL = lane >> 2;
    int b0 = (lane & 3) * 2;

    for (int i = 0; i < 256; i++) {
        int e = e0 + warp * 256 + i;
        if (e >= EE) break;
        int2 ed = g_sorted[e];
        float v = 0.0f;
        if (lane < 8)       v = g_r[ed.x * 8 + lane];
        else if (lane < 16) v = g_r[ed.y * 8 + (lane - 8)];
        float rs  = __shfl_sync(0xFFFFFFFFu, v, aL);
        float rd0 = __shfl_sync(0xFFFFFFFFu, v, 8 + b0);
        float rd1 = __shfl_sync(0xFFFFFFFFu, v, 8 + b0 + 1);
        int gs = graph_of(ed.x), gd = graph_of(ed.y);
        int slot = gd - g0;
        int row = (gs << 3) + aL;
        float v0 = rs * rd0, v1 = rs * rd1;
        if (slot >= 0 && slot < 2) {
            atomicAdd(&acc[slot * 2048 + row * 8 + b0],     v0);
            atomicAdd(&acc[slot * 2048 + row * 8 + b0 + 1], v1);
        } else {
            atomicAdd(out + row * 256 + (gd << 3) + b0,     v0);
            atomicAdd(out + row * 256 + (gd << 3) + b0 + 1, v1);
        }
    }
    __syncthreads();
    for (int idx = tid; idx < 4096; idx += 256) {
        float s = acc[idx];
        int slot = idx >> 11, rest = idx & 2047, row = rest >> 3, bc = rest & 7;
        int gg = g0 + slot;
        if (gg < NB && s != 0.0f)
            atomicAdd(out + row * 256 + (gg << 3) + bc, s);
    }
}

// ---------------------------------------------------------------- launch
extern "C" void kernel_launch(void* const* d_in, const int* in_sizes, int n_in,
                              void* d_out, int out_size) {
    const float* x  = (const float*)d_in[0];
    const int*   ei = (const int*)d_in[1];
    const float* We = (const float*)d_in[3];
    const float* be = (const float*)d_in[4];
    const float* Wp = (const float*)d_in[5];
    const float* bp = (const float*)d_in[6];
    float* out = (float*)d_out;

    static int smem_set = 0;
    if (!smem_set) {
        cudaFuncSetAttribute(k_fused, cudaFuncAttributeMaxDynamicSharedMemorySize,
                             FS_WORDS * 4);
        smem_set = 1;
    }

    k_init<<<482, 512>>>(out, We, Wp);
    k_prepX<<<(NN * INF + 255) / 256, 256>>>(x);
    k_hist<<<(EE + 255) / 256, 256>>>(ei);
    k_scan<<<1, 1024>>>();
    k_scatter<<<(EE + 255) / 256, 256>>>(ei);
    k_neigh<<<(NN + 7) / 8, 256>>>(x);
    k_fused<<<NN2 / 64, 256, FS_WORDS * 4>>>(be, bp, out);
    k_adj<<<(EE + 2047) / 2048, 256>>>(out);
}

// round 7
// speedup vs baseline: 1.3724x; 1.3724x over previous
#include <cuda_runtime.h>

#define NN 50000
#define NN2 50176          // padded rows (pad stays zero)
#define EE 800000
#define INF 128
#define NB 32
#define H_OFF 65536        // h starts after adj (256*256)
#define OUT_ELEMS 98304    // 256*256 + 256*128
#define WELEMS 98304       // 384*256 weight elements

__device__ __forceinline__ int graph_of(int n) { return (n * NB) / NN; }

// ---- scratch (module globals; zero-initialized, no runtime allocation) ----
__device__ float g_Z[(size_t)NN * 384];
__device__ float g_r[NN * 8];
__device__ int   g_counts[53248];
__device__ int   g_off[NN + 1];
__device__ int   g_cursor[NN];
__device__ int   g_bsum[64];
__device__ int   g_boff[64];
__device__ int2  g_sorted[EE];
__device__ unsigned int g_A32[(size_t)NN2 * 256];  // tf32 [x | neigh]
__device__ unsigned int g_BT[384 * 256];           // tf32 W^T: [n][k]

// ================= helpers =================
__device__ __forceinline__ unsigned int smem_u32(const void* p) {
    unsigned int a;
    asm("{ .reg .u64 t; cvta.to.shared.u64 t, %1; cvt.u32.u64 %0, t; }" : "=r"(a) : "l"(p));
    return a;
}
__device__ __forceinline__ unsigned int f2tf32(float v) {
    unsigned int o;
    asm("cvt.rna.tf32.f32 %0, %1;" : "=r"(o) : "f"(v));
    return o;
}
#define CP_ASYNC16(dst, src) \
    asm volatile("cp.async.ca.shared.global [%0], [%1], 16;" :: "r"(dst), "l"(src) : "memory")
#define CP_COMMIT()  asm volatile("cp.async.commit_group;" ::: "memory")
#define CP_WAIT1()   asm volatile("cp.async.wait_group 1;" ::: "memory")
#define CP_WAIT0()   asm volatile("cp.async.wait_group 0;" ::: "memory")

__device__ __forceinline__ void mma16n8k8(float* d, const unsigned* a, const unsigned* b) {
    asm volatile(
        "mma.sync.aligned.m16n8k8.row.col.f32.tf32.tf32.f32 "
        "{%0,%1,%2,%3}, {%4,%5,%6,%7}, {%8,%9}, {%0,%1,%2,%3};"
        : "+f"(d[0]), "+f"(d[1]), "+f"(d[2]), "+f"(d[3])
        : "r"(a[0]), "r"(a[1]), "r"(a[2]), "r"(a[3]), "r"(b[0]), "r"(b[1]));
}

// ---------------------------------------------------------------- init: zero counts+out, convert W
__global__ void k_init(float* __restrict__ out,
                       const float* __restrict__ We, const float* __restrict__ Wp) {
    int i = blockIdx.x * blockDim.x + threadIdx.x;
    const int total = NN + OUT_ELEMS + WELEMS;
    for (; i < total; i += gridDim.x * blockDim.x) {
        if (i < NN) g_counts[i] = 0;
        else if (i < NN + OUT_ELEMS) out[i - NN] = 0.0f;
        else {
            int idx = i - NN - OUT_ELEMS;
            int k = idx & 255, n = idx >> 8;
            float v = (n < 128) ? We[k * 128 + n] : Wp[k * 256 + (n - 128)];
            g_BT[n * 256 + k] = f2tf32(v);
        }
    }
}

// ---------------------------------------------------------------- prep X: tf32 image (cols 0..127)
__global__ void k_prepX(const float* __restrict__ x) {
    int i = blockIdx.x * 256 + threadIdx.x;
    if (i < NN * INF) {
        int row = i >> 7, col = i & 127;
        g_A32[(size_t)row * 256 + col] = f2tf32(x[i]);
    }
}

// ---------------------------------------------------------------- histogram of dst
__global__ void k_hist(const int* __restrict__ ei) {
    int e = blockIdx.x * 256 + threadIdx.x;
    if (e < EE) atomicAdd(&g_counts[ei[EE + e]], 1);
}

// ---------------------------------------------------------------- parallel scan, 3 stages
__global__ void k_scan1() {          // 49 blocks x 1024: local excl scan + block total
    int tid = threadIdx.x, lane = tid & 31, wid = tid >> 5;
    int idx = blockIdx.x * 1024 + tid;
    int v = (idx < NN) ? g_counts[idx] : 0;
    int s = v;
    #pragma unroll
    for (int o = 1; o < 32; o <<= 1) {
        int u = __shfl_up_sync(0xFFFFFFFFu, s, o);
        if (lane >= o) s += u;
    }
    __shared__ int ws[32];
    if (lane == 31) ws[wid] = s;
    __syncthreads();
    if (wid == 0) {
        int u = ws[lane];
        #pragma unroll
        for (int o = 1; o < 32; o <<= 1) {
            int q = __shfl_up_sync(0xFFFFFFFFu, u, o);
            if (lane >= o) u += q;
        }
        ws[lane] = u;
    }
    __syncthreads();
    int excl = s - v + (wid ? ws[wid - 1] : 0);
    if (idx < NN) g_off[idx] = excl;
    if (tid == 1023) g_bsum[blockIdx.x] = excl + v;
}
__global__ void k_scan2() {          // 1 block: excl scan of 49 block sums
    int lane = threadIdx.x;
    int v = (lane < 49) ? g_bsum[lane] : 0;
    int s = v;
    #pragma unroll
    for (int o = 1; o < 32; o <<= 1) {
        int u = __shfl_up_sync(0xFFFFFFFFu, s, o);
        if ((lane & 31) >= o) s += u;
    }
    __shared__ int w0;
    if (lane == 31) w0 = s;
    __syncthreads();
    int excl = s - v + ((lane >= 32) ? w0 : 0);
    if (lane < 49) g_boff[lane] = excl;
}
__global__ void k_scan3() {          // add block offsets, init cursor
    int idx = blockIdx.x * 256 + threadIdx.x;
    if (idx < NN) {
        int v = g_off[idx] + g_boff[idx >> 10];
        g_off[idx] = v;
        g_cursor[idx] = v;
    }
    if (idx == 0) g_off[NN] = EE;
}

// ---------------------------------------------------------------- scatter into dst-sorted order
__global__ void k_scatter(const int* __restrict__ ei) {
    int e = blockIdx.x * 256 + threadIdx.x;
    if (e < EE) {
        int s = ei[e], d = ei[EE + e];
        int pos = atomicAdd(&g_cursor[d], 1);
        g_sorted[pos] = make_int2(s, d);
    }
}

// ---------------------------------------------------------------- mean aggregation -> tf32 cols 128..255
__global__ void k_neigh(const float* __restrict__ x) {
    int node = blockIdx.x * 8 + (threadIdx.x >> 5);
    if (node >= NN) return;
    int lane = threadIdx.x & 31;
    int b = g_off[node], e = g_off[node + 1];
    float4 a0 = make_float4(0.f, 0.f, 0.f, 0.f);
    float4 a1 = make_float4(0.f, 0.f, 0.f, 0.f);
    int j = b;
    for (; j + 1 < e; j += 2) {
        int s0 = g_sorted[j].x, s1 = g_sorted[j + 1].x;
        float4 v0 = *reinterpret_cast<const float4*>(x + (size_t)s0 * INF + lane * 4);
        float4 v1 = *reinterpret_cast<const float4*>(x + (size_t)s1 * INF + lane * 4);
        a0.x += v0.x; a0.y += v0.y; a0.z += v0.z; a0.w += v0.w;
        a1.x += v1.x; a1.y += v1.y; a1.z += v1.z; a1.w += v1.w;
    }
    if (j < e) {
        int s0 = g_sorted[j].x;
        float4 v0 = *reinterpret_cast<const float4*>(x + (size_t)s0 * INF + lane * 4);
        a0.x += v0.x; a0.y += v0.y; a0.z += v0.z; a0.w += v0.w;
    }
    float inv = 1.0f / (float)max(e - b, 1);
    uint4 tv;
    tv.x = f2tf32((a0.x + a1.x) * inv); tv.y = f2tf32((a0.y + a1.y) * inv);
    tv.z = f2tf32((a0.z + a1.z) * inv); tv.w = f2tf32((a0.w + a1.w) * inv);
    *reinterpret_cast<uint4*>(g_A32 + (size_t)node * 256 + 128 + lane * 4) = tv;
}

// ---------------------------------------------------------------- GEMM via mma.sync tf32 (XOR swizzle)
// CTA: 128x128, K=256 in 8 chunks of 32, cp.async double buffer.
// SMEM words: A bufs @ 0,4096; B bufs @ 8192,12288 (128 rows x 32 words, chunk^row&7).
#define SM_WORDS 16384
__global__ __launch_bounds__(256, 2) void k_gemm_mma(const float* __restrict__ be,
                                                     const float* __restrict__ bp) {
    extern __shared__ unsigned int sm[];
    int tid = threadIdx.x, lane = tid & 31, wid = tid >> 5;
    int warp_m = wid >> 1, warp_n = wid & 1;
    int g = lane >> 2, t = lane & 3;
    int m0 = blockIdx.x * 128, bt = blockIdx.y;
    const unsigned int* Bg = g_BT + (size_t)bt * 128 * 256;
    unsigned int sbase = smem_u32(sm);

    float acc[2][8][4];
    #pragma unroll
    for (int mt = 0; mt < 2; mt++)
        #pragma unroll
        for (int nt = 0; nt < 8; nt++)
            #pragma unroll
            for (int j = 0; j < 4; j++) acc[mt][nt][j] = 0.0f;

    auto load_chunk = [&](int c, int buf) {
        int k0 = c * 32;
        unsigned int sa = sbase + (buf * 4096) * 4;
        unsigned int sb = sbase + ((8192 + buf * 4096)) * 4;
        #pragma unroll
        for (int i = 0; i < 4; i++) {
            int e = tid + i * 256;             // 0..1023
            int m = e >> 3, ch = e & 7;
            unsigned int soff = (m * 32 + ((ch ^ (m & 7)) << 2)) * 4;
            CP_ASYNC16(sa + soff, g_A32 + (size_t)(m0 + m) * 256 + k0 + ch * 4);
            CP_ASYNC16(sb + soff, Bg + (size_t)m * 256 + k0 + ch * 4);
        }
    };
    auto compute = [&](int buf) {
        const unsigned int* As = sm + buf * 4096;
        const unsigned int* Bs = sm + 8192 + buf * 4096;
        #pragma unroll
        for (int ks = 0; ks < 4; ks++) {
            int c0 = 2 * ks, c1 = 2 * ks + 1;
            unsigned int a[2][4], b[8][2];
            #pragma unroll
            for (int mt = 0; mt < 2; mt++) {
                int r0 = warp_m * 32 + mt * 16 + g;   // r0&7 == g
                int r1 = r0 + 8;
                a[mt][0] = As[r0 * 32 + ((c0 ^ g) << 2) + t];
                a[mt][1] = As[r1 * 32 + ((c0 ^ g) << 2) + t];
                a[mt][2] = As[r0 * 32 + ((c1 ^ g) << 2) + t];
                a[mt][3] = As[r1 * 32 + ((c1 ^ g) << 2) + t];
            }
            #pragma unroll
            for (int nt = 0; nt < 8; nt++) {
                int n = warp_n * 64 + nt * 8 + g;     // n&7 == g
                b[nt][0] = Bs[n * 32 + ((c0 ^ g) << 2) + t];
                b[nt][1] = Bs[n * 32 + ((c1 ^ g) << 2) + t];
            }
            #pragma unroll
            for (int mt = 0; mt < 2; mt++)
                #pragma unroll
                for (int nt = 0; nt < 8; nt++)
                    mma16n8k8(acc[mt][nt], a[mt], b[nt]);
        }
    };

    load_chunk(0, 0); CP_COMMIT();
    load_chunk(1, 1); CP_COMMIT();
    #pragma unroll
    for (int c = 0; c < 8; c++) {
        if (c < 7) { CP_WAIT1(); } else { CP_WAIT0(); }
        __syncthreads();
        compute(c & 1);
        __syncthreads();
        if (c + 2 < 8) { load_chunk(c + 2, c & 1); CP_COMMIT(); }
    }

    // ---- epilogue: bias + store ----
    __syncthreads();
    float* bsh = reinterpret_cast<float*>(sm);
    const float* bias = (bt == 0) ? be : bp + (bt - 1) * 128;
    if (tid < 128) bsh[tid] = bias[tid];
    __syncthreads();
    #pragma unroll
    for (int mt = 0; mt < 2; mt++) {
        int r0 = m0 + warp_m * 32 + mt * 16 + g;
        #pragma unroll
        for (int nt = 0; nt < 8; nt++) {
            int cloc = warp_n * 64 + nt * 8 + 2 * t;
            float bx = bsh[cloc], by = bsh[cloc + 1];
            if (r0 < NN) {
                float2 v = make_float2(acc[mt][nt][0] + bx, acc[mt][nt][1] + by);
                *reinterpret_cast<float2*>(g_Z + (size_t)r0 * 384 + bt * 128 + cloc) = v;
            }
            if (r0 + 8 < NN) {
                float2 v = make_float2(acc[mt][nt][2] + bx, acc[mt][nt][3] + by);
                *reinterpret_cast<float2*>(g_Z + (size_t)(r0 + 8) * 384 + bt * 128 + cloc) = v;
            }
        }
    }
}

// ---------------------------------------------------------------- per-node: softmax -> r, accumulate h
__global__ __launch_bounds__(128) void k_node(float* __restrict__ out) {
    __shared__ float acc[4][2048];
    int tid = threadIdx.x, warp = tid >> 5, lane = tid & 31;
    int n0 = blockIdx.x * 128;
    int g0 = graph_of(n0);
    for (int i = tid; i < 4 * 2048; i += 128) (&acc[0][0])[i] = 0.0f;
    __syncthreads();
    float* ac = acc[warp];

    for (int it = 0; it < 32; it++) {
        int n = n0 + warp * 32 + it;
        if (n >= NN) break;
        const float* zr = g_Z + (size_t)n * 384;
        float l[8];
        float4 q0 = *reinterpret_cast<const float4*>(zr + 128 + lane * 8);
        float4 q1 = *reinterpret_cast<const float4*>(zr + 128 + lane * 8 + 4);
        l[0] = q0.x; l[1] = q0.y; l[2] = q0.z; l[3] = q0.w;
        l[4] = q1.x; l[5] = q1.y; l[6] = q1.z; l[7] = q1.w;
        float mx = l[0];
        #pragma unroll
        for (int j = 1; j < 8; j++) mx = fmaxf(mx, l[j]);
        #pragma unroll
        for (int o = 16; o > 0; o >>= 1) mx = fmaxf(mx, __shfl_xor_sync(0xFFFFFFFFu, mx, o));
        float ex[8], s = 0.0f;
        #pragma unroll
        for (int j = 0; j < 8; j++) { ex[j] = expf(l[j] - mx); s += ex[j]; }
        #pragma unroll
        for (int o = 16; o > 0; o >>= 1) s += __shfl_xor_sync(0xFFFFFFFFu, s, o);
        float inv_s = 1.0f / s;
        float p[8], pm = -1e30f;
        #pragma unroll
        for (int j = 0; j < 8; j++) { p[j] = ex[j] * inv_s; pm = fmaxf(pm, p[j]); }
        float e2[8], se2 = 0.0f;
        #pragma unroll
        for (int j = 0; j < 8; j++) { e2[j] = expf(p[j] - pm); se2 += e2[j]; }
        float Zf = se2 + 248.0f * expf(-pm);
        float invZ = 1.0f / Zf;
        float invd = 1.0f / (se2 * invZ + 1e-13f);
        float r[8];
        #pragma unroll
        for (int j = 0; j < 8; j++) r[j] = e2[j] * invZ * invd;

        int gn = graph_of(n);
        if (lane == gn) {
            #pragma unroll
            for (int j = 0; j < 8; j++) g_r[n * 8 + j] = r[j];
        }
        float rb[8];
        #pragma unroll
        for (int j = 0; j < 8; j++) rb[j] = __shfl_sync(0xFFFFFFFFu, r[j], gn);

        float4 ev = *reinterpret_cast<const float4*>(zr + lane * 4);
        int slot = gn - g0;
        float4* a4 = reinterpret_cast<float4*>(ac + slot * 1024) + lane;
        #pragma unroll
        for (int a = 0; a < 8; a++) {
            float ra = rb[a];
            float4 t = a4[a * 32];
            t.x = fmaf(ra, ev.x, t.x);
            t.y = fmaf(ra, ev.y, t.y);
            t.z = fmaf(ra, ev.z, t.z);
            t.w = fmaf(ra, ev.w, t.w);
            a4[a * 32] = t;
        }
    }
    __syncthreads();
    for (int idx = tid; idx < 2048; idx += 128) {
        float s = acc[0][idx] + acc[1][idx] + acc[2][idx] + acc[3][idx];
        int slot = idx >> 10, rest = idx & 1023, a = rest >> 7, c = rest & 127;
        int gg = g0 + slot;
        if (gg < NB && s != 0.0f)
            atomicAdd(out + H_OFF + ((gg << 3) + a) * 128 + c, s);
    }
}

// ---------------------------------------------------------------- per-edge adj: 8x8 outer products
__global__ __launch_bounds__(256) void k_adj(float* __restrict__ out) {
    __shared__ float acc[2 * 2048];
    int tid = threadIdx.x;
    for (int i = tid; i < 4096; i += 256) acc[i] = 0.0f;
    __syncthreads();
    int e0 = blockIdx.x * 2048;
    int g0 = graph_of(g_sorted[e0].y);
    int warp = tid >> 5, lane = tid & 31;
    int aL = lane >> 2;
    int b0 = (lane & 3) * 2;

    for (int i = 0; i < 256; i++) {
        int e = e0 + warp * 256 + i;
        if (e >= EE) break;
        int2 ed = g_sorted[e];
        float v = 0.0f;
        if (lane < 8)       v = g_r[ed.x * 8 + lane];
        else if (lane < 16) v = g_r[ed.y * 8 + (lane - 8)];
        float rs  = __shfl_sync(0xFFFFFFFFu, v, aL);
        float rd0 = __shfl_sync(0xFFFFFFFFu, v, 8 + b0);
        float rd1 = __shfl_sync(0xFFFFFFFFu, v, 8 + b0 + 1);
        int gs = graph_of(ed.x), gd = graph_of(ed.y);
        int slot = gd - g0;
        int row = (gs << 3) + aL;
        float v0 = rs * rd0, v1 = rs * rd1;
        if (slot >= 0 && slot < 2) {
            atomicAdd(&acc[slot * 2048 + row * 8 + b0],     v0);
            atomicAdd(&acc[slot * 2048 + row * 8 + b0 + 1], v1);
        } else {
            atomicAdd(out + row * 256 + (gd << 3) + b0,     v0);
            atomicAdd(out + row * 256 + (gd << 3) + b0 + 1, v1);
        }
    }
    __syncthreads();
    for (int idx = tid; idx < 4096; idx += 256) {
        float s = acc[idx];
        int slot = idx >> 11, rest = idx & 2047, row = rest >> 3, bc = rest & 7;
        int gg = g0 + slot;
        if (gg < NB && s != 0.0f)
            atomicAdd(out + row * 256 + (gg << 3) + bc, s);
    }
}

// ---------------------------------------------------------------- launch
extern "C" void kernel_launch(void* const* d_in, const int* in_sizes, int n_in,
                              void* d_out, int out_size) {
    const float* x  = (const float*)d_in[0];
    const int*   ei = (const int*)d_in[1];
    const float* We = (const float*)d_in[3];
    const float* be = (const float*)d_in[4];
    const float* Wp = (const float*)d_in[5];
    const float* bp = (const float*)d_in[6];
    float* out = (float*)d_out;

    static int smem_set = 0;
    if (!smem_set) {
        cudaFuncSetAttribute(k_gemm_mma, cudaFuncAttributeMaxDynamicSharedMemorySize,
                             SM_WORDS * 4);
        smem_set = 1;
    }

    k_init<<<482, 512>>>(out, We, Wp);
    k_prepX<<<(NN * INF + 255) / 256, 256>>>(x);
    k_hist<<<(EE + 255) / 256, 256>>>(ei);
    k_scan1<<<49, 1024>>>();
    k_scan2<<<1, 64>>>();
    k_scan3<<<(NN + 255) / 256, 256>>>();
    k_scatter<<<(EE + 255) / 256, 256>>>(ei);
    k_neigh<<<(NN + 7) / 8, 256>>>(x);
    dim3 gg((NN + 127) / 128, 3);
    k_gemm_mma<<<gg, 256, SM_WORDS * 4>>>(be, bp);
    k_node<<<(NN + 127) / 128, 128>>>(out);
    k_adj<<<(EE + 2047) / 2048, 256>>>(out);
}

// round 8
// speedup vs baseline: 1.3756x; 1.0024x over previous
#include <cuda_runtime.h>

#define NN 50000
#define NN2 50176
#define EE 800000
#define INF 128
#define NB 32
#define H_OFF 65536        // h starts after adj (256*256)
#define OUT_ELEMS 98304    // 256*256 + 256*128
#define WELEMS 98304       // 384*256 weight elements
#define XELEMS (NN * INF)  // 6.4M

__device__ __forceinline__ int graph_of(int n) { return (n * NB) / NN; }

// ---- scratch (module globals; zero-initialized, no runtime allocation) ----
__device__ float g_Z[(size_t)NN * 384];
__device__ float g_r[NN * 8];
__device__ int   g_counts[53248];      // zero at entry: static init, then re-zeroed by k_scan1
__device__ int   g_off[NN + 1];
__device__ int   g_cursor[NN];
__device__ int   g_bsum[64];
__device__ int   g_boff[64];
__device__ int2  g_sorted[EE];
__device__ unsigned int g_A32[(size_t)NN2 * 256];  // tf32 [x | neigh]
__device__ unsigned int g_BT[384 * 256];           // tf32 W^T: [n][k]

// ================= helpers =================
__device__ __forceinline__ unsigned int smem_u32(const void* p) {
    unsigned int a;
    asm("{ .reg .u64 t; cvta.to.shared.u64 t, %1; cvt.u32.u64 %0, t; }" : "=r"(a) : "l"(p));
    return a;
}
__device__ __forceinline__ unsigned int f2tf32(float v) {
    unsigned int o;
    asm("cvt.rna.tf32.f32 %0, %1;" : "=r"(o) : "f"(v));
    return o;
}
#define CP_ASYNC16(dst, src) \
    asm volatile("cp.async.ca.shared.global [%0], [%1], 16;" :: "r"(dst), "l"(src) : "memory")
#define CP_COMMIT()  asm volatile("cp.async.commit_group;" ::: "memory")
#define CP_WAIT1()   asm volatile("cp.async.wait_group 1;" ::: "memory")
#define CP_WAIT0()   asm volatile("cp.async.wait_group 0;" ::: "memory")

__device__ __forceinline__ void mma16n8k8(float* d, const unsigned* a, const unsigned* b) {
    asm volatile(
        "mma.sync.aligned.m16n8k8.row.col.f32.tf32.tf32.f32 "
        "{%0,%1,%2,%3}, {%4,%5,%6,%7}, {%8,%9}, {%0,%1,%2,%3};"
        : "+f"(d[0]), "+f"(d[1]), "+f"(d[2]), "+f"(d[3])
        : "r"(a[0]), "r"(a[1]), "r"(a[2]), "r"(a[3]), "r"(b[0]), "r"(b[1]));
}

// ---------------------------------------------------------------- init: zero out, W cvt, prepX, hist
// g_counts is guaranteed zero at entry (static init on first call; k_scan1 re-zeroes after use).
__global__ void k_init(float* __restrict__ out,
                       const float* __restrict__ We, const float* __restrict__ Wp,
                       const float* __restrict__ x, const int* __restrict__ ei) {
    int i = blockIdx.x * blockDim.x + threadIdx.x;
    if (i < OUT_ELEMS) {
        out[i] = 0.0f;
    } else if (i < OUT_ELEMS + WELEMS) {
        int idx = i - OUT_ELEMS;
        int k = idx & 255, n = idx >> 8;
        float v = (n < 128) ? We[k * 128 + n] : Wp[k * 256 + (n - 128)];
        g_BT[n * 256 + k] = f2tf32(v);
    } else if (i < OUT_ELEMS + WELEMS + XELEMS) {
        int idx = i - OUT_ELEMS - WELEMS;
        int row = idx >> 7, col = idx & 127;
        g_A32[(size_t)row * 256 + col] = f2tf32(x[idx]);
    } else if (i < OUT_ELEMS + WELEMS + XELEMS + EE) {
        int e = i - OUT_ELEMS - WELEMS - XELEMS;
        atomicAdd(&g_counts[ei[EE + e]], 1);
    }
}

// ---------------------------------------------------------------- parallel scan, 3 stages
__global__ void k_scan1() {          // local excl scan + block total; re-zero counts
    int tid = threadIdx.x, lane = tid & 31, wid = tid >> 5;
    int idx = blockIdx.x * 1024 + tid;
    int v = (idx < NN) ? g_counts[idx] : 0;
    if (idx < NN) g_counts[idx] = 0;         // restore for next kernel_launch call
    int s = v;
    #pragma unroll
    for (int o = 1; o < 32; o <<= 1) {
        int u = __shfl_up_sync(0xFFFFFFFFu, s, o);
        if (lane >= o) s += u;
    }
    __shared__ int ws[32];
    if (lane == 31) ws[wid] = s;
    __syncthreads();
    if (wid == 0) {
        int u = ws[lane];
        #pragma unroll
        for (int o = 1; o < 32; o <<= 1) {
            int q = __shfl_up_sync(0xFFFFFFFFu, u, o);
            if (lane >= o) u += q;
        }
        ws[lane] = u;
    }
    __syncthreads();
    int excl = s - v + (wid ? ws[wid - 1] : 0);
    if (idx < NN) g_off[idx] = excl;
    if (tid == 1023) g_bsum[blockIdx.x] = excl + v;
}
__global__ void k_scan2() {          // 1 block: excl scan of 49 block sums
    int lane = threadIdx.x;
    int v = (lane < 49) ? g_bsum[lane] : 0;
    int s = v;
    #pragma unroll
    for (int o = 1; o < 32; o <<= 1) {
        int u = __shfl_up_sync(0xFFFFFFFFu, s, o);
        if ((lane & 31) >= o) s += u;
    }
    __shared__ int w0;
    if (lane == 31) w0 = s;
    __syncthreads();
    int excl = s - v + ((lane >= 32) ? w0 : 0);
    if (lane < 49) g_boff[lane] = excl;
}
__global__ void k_scan3() {          // add block offsets, init cursor
    int idx = blockIdx.x * 256 + threadIdx.x;
    if (idx < NN) {
        int v = g_off[idx] + g_boff[idx >> 10];
        g_off[idx] = v;
        g_cursor[idx] = v;
    }
    if (idx == 0) g_off[NN] = EE;
}

// ---------------------------------------------------------------- scatter into dst-sorted order
__global__ void k_scatter(const int* __restrict__ ei) {
    int e = blockIdx.x * 256 + threadIdx.x;
    if (e < EE) {
        int s = ei[e], d = ei[EE + e];
        int pos = atomicAdd(&g_cursor[d], 1);
        g_sorted[pos] = make_int2(s, d);
    }
}

// ---------------------------------------------------------------- mean aggregation -> tf32 cols 128..255
__global__ void k_neigh(const float* __restrict__ x) {
    int node = blockIdx.x * 8 + (threadIdx.x >> 5);
    if (node >= NN) return;
    int lane = threadIdx.x & 31;
    int b = g_off[node], e = g_off[node + 1];
    float4 a0 = make_float4(0.f, 0.f, 0.f, 0.f);
    float4 a1 = make_float4(0.f, 0.f, 0.f, 0.f);
    float4 a2 = make_float4(0.f, 0.f, 0.f, 0.f);
    float4 a3 = make_float4(0.f, 0.f, 0.f, 0.f);
    int j = b;
    for (; j + 3 < e; j += 4) {
        int s0 = g_sorted[j].x, s1 = g_sorted[j + 1].x;
        int s2 = g_sorted[j + 2].x, s3 = g_sorted[j + 3].x;
        float4 v0 = *reinterpret_cast<const float4*>(x + (size_t)s0 * INF + lane * 4);
        float4 v1 = *reinterpret_cast<const float4*>(x + (size_t)s1 * INF + lane * 4);
        float4 v2 = *reinterpret_cast<const float4*>(x + (size_t)s2 * INF + lane * 4);
        float4 v3 = *reinterpret_cast<const float4*>(x + (size_t)s3 * INF + lane * 4);
        a0.x += v0.x; a0.y += v0.y; a0.z += v0.z; a0.w += v0.w;
        a1.x += v1.x; a1.y += v1.y; a1.z += v1.z; a1.w += v1.w;
        a2.x += v2.x; a2.y += v2.y; a2.z += v2.z; a2.w += v2.w;
        a3.x += v3.x; a3.y += v3.y; a3.z += v3.z; a3.w += v3.w;
    }
    for (; j < e; j++) {
        int s0 = g_sorted[j].x;
        float4 v0 = *reinterpret_cast<const float4*>(x + (size_t)s0 * INF + lane * 4);
        a0.x += v0.x; a0.y += v0.y; a0.z += v0.z; a0.w += v0.w;
    }
    float inv = 1.0f / (float)max(e - b, 1);
    uint4 tv;
    tv.x = f2tf32((a0.x + a1.x + a2.x + a3.x) * inv);
    tv.y = f2tf32((a0.y + a1.y + a2.y + a3.y) * inv);
    tv.z = f2tf32((a0.z + a1.z + a2.z + a3.z) * inv);
    tv.w = f2tf32((a0.w + a1.w + a2.w + a3.w) * inv);
    *reinterpret_cast<uint4*>(g_A32 + (size_t)node * 256 + 128 + lane * 4) = tv;
}

// ---------------------------------------------------------------- GEMM via mma.sync tf32 (XOR swizzle)
// CTA: 128x128, K=256 in 8 chunks of 32, cp.async 3-stage pipeline, 1 sync/chunk.
// SMEM words: A stage s @ s*4096; B stage s @ 12288 + s*4096. Total 24576 words = 96KB.
#define SM_WORDS 24576
__global__ __launch_bounds__(256, 2) void k_gemm_mma(const float* __restrict__ be,
                                                     const float* __restrict__ bp) {
    extern __shared__ unsigned int sm[];
    int tid = threadIdx.x, lane = tid & 31, wid = tid >> 5;
    int warp_m = wid >> 1, warp_n = wid & 1;
    int g = lane >> 2, t = lane & 3;
    int m0 = blockIdx.x * 128, bt = blockIdx.y;
    const unsigned int* Bg = g_BT + (size_t)bt * 128 * 256;
    unsigned int sbase = smem_u32(sm);

    float acc[2][8][4];
    #pragma unroll
    for (int mt = 0; mt < 2; mt++)
        #pragma unroll
        for (int nt = 0; nt < 8; nt++)
            #pragma unroll
            for (int j = 0; j < 4; j++) acc[mt][nt][j] = 0.0f;

    auto load_chunk = [&](int c, int s) {
        int k0 = c * 32;
        unsigned int sa = sbase + (s * 4096) * 4;
        unsigned int sb = sbase + ((12288 + s * 4096)) * 4;
        #pragma unroll
        for (int i = 0; i < 4; i++) {
            int e = tid + i * 256;             // 0..1023
            int m = e >> 3, ch = e & 7;
            unsigned int soff = (m * 32 + ((ch ^ (m & 7)) << 2)) * 4;
            CP_ASYNC16(sa + soff, g_A32 + (size_t)(m0 + m) * 256 + k0 + ch * 4);
            CP_ASYNC16(sb + soff, Bg + (size_t)m * 256 + k0 + ch * 4);
        }
    };
    auto compute = [&](int s) {
        const unsigned int* As = sm + s * 4096;
        const unsigned int* Bs = sm + 12288 + s * 4096;
        #pragma unroll
        for (int ks = 0; ks < 4; ks++) {
            int c0 = 2 * ks, c1 = 2 * ks + 1;
            unsigned int a[2][4], b[8][2];
            #pragma unroll
            for (int mt = 0; mt < 2; mt++) {
                int r0 = warp_m * 32 + mt * 16 + g;   // r0&7 == g
                int r1 = r0 + 8;
                a[mt][0] = As[r0 * 32 + ((c0 ^ g) << 2) + t];
                a[mt][1] = As[r1 * 32 + ((c0 ^ g) << 2) + t];
                a[mt][2] = As[r0 * 32 + ((c1 ^ g) << 2) + t];
                a[mt][3] = As[r1 * 32 + ((c1 ^ g) << 2) + t];
            }
            #pragma unroll
            for (int nt = 0; nt < 8; nt++) {
                int n = warp_n * 64 + nt * 8 + g;     // n&7 == g
                b[nt][0] = Bs[n * 32 + ((c0 ^ g) << 2) + t];
                b[nt][1] = Bs[n * 32 + ((c1 ^ g) << 2) + t];
            }
            #pragma unroll
            for (int mt = 0; mt < 2; mt++)
                #pragma unroll
                for (int nt = 0; nt < 8; nt++)
                    mma16n8k8(acc[mt][nt], a[mt], b[nt]);
        }
    };

    load_chunk(0, 0); CP_COMMIT();
    load_chunk(1, 1); CP_COMMIT();
    #pragma unroll
    for (int c = 0; c < 8; c++) {
        if (c < 7) { CP_WAIT1(); } else { CP_WAIT0(); }
        __syncthreads();
        compute(c % 3);
        if (c + 2 < 8) { load_chunk(c + 2, (c + 2) % 3); CP_COMMIT(); }
    }

    // ---- epilogue: bias + store ----
    __syncthreads();
    float* bsh = reinterpret_cast<float*>(sm);
    const float* bias = (bt == 0) ? be : bp + (bt - 1) * 128;
    if (tid < 128) bsh[tid] = bias[tid];
    __syncthreads();
    #pragma unroll
    for (int mt = 0; mt < 2; mt++) {
        int r0 = m0 + warp_m * 32 + mt * 16 + g;
        #pragma unroll
        for (int nt = 0; nt < 8; nt++) {
            int cloc = warp_n * 64 + nt * 8 + 2 * t;
            float bx = bsh[cloc], by = bsh[cloc + 1];
            if (r0 < NN) {
                float2 v = make_float2(acc[mt][nt][0] + bx, acc[mt][nt][1] + by);
                *reinterpret_cast<float2*>(g_Z + (size_t)r0 * 384 + bt * 128 + cloc) = v;
            }
            if (r0 + 8 < NN) {
                float2 v = make_float2(acc[mt][nt][2] + bx, acc[mt][nt][3] + by);
                *reinterpret_cast<float2*>(g_Z + (size_t)(r0 + 8) * 384 + bt * 128 + cloc) = v;
            }
        }
    }
}

// ---------------------------------------------------------------- per-node: softmax -> r, accumulate h
__global__ __launch_bounds__(128) void k_node(float* __restrict__ out) {
    __shared__ float acc[4][2048];
    int tid = threadIdx.x, warp = tid >> 5, lane = tid & 31;
    int n0 = blockIdx.x * 128;
    int g0 = graph_of(n0);
    for (int i = tid; i < 4 * 2048; i += 128) (&acc[0][0])[i] = 0.0f;
    __syncthreads();
    float* ac = acc[warp];

    for (int it = 0; it < 32; it++) {
        int n = n0 + warp * 32 + it;
        if (n >= NN) break;
        const float* zr = g_Z + (size_t)n * 384;
        float l[8];
        float4 q0 = *reinterpret_cast<const float4*>(zr + 128 + lane * 8);
        float4 q1 = *reinterpret_cast<const float4*>(zr + 128 + lane * 8 + 4);
        l[0] = q0.x; l[1] = q0.y; l[2] = q0.z; l[3] = q0.w;
        l[4] = q1.x; l[5] = q1.y; l[6] = q1.z; l[7] = q1.w;
        float mx = l[0];
        #pragma unroll
        for (int j = 1; j < 8; j++) mx = fmaxf(mx, l[j]);
        #pragma unroll
        for (int o = 16; o > 0; o >>= 1) mx = fmaxf(mx, __shfl_xor_sync(0xFFFFFFFFu, mx, o));
        float ex[8], s = 0.0f;
        #pragma unroll
        for (int j = 0; j < 8; j++) { ex[j] = expf(l[j] - mx); s += ex[j]; }
        #pragma unroll
        for (int o = 16; o > 0; o >>= 1) s += __shfl_xor_sync(0xFFFFFFFFu, s, o);
        float inv_s = 1.0f / s;
        float p[8], pm = -1e30f;
        #pragma unroll
        for (int j = 0; j < 8; j++) { p[j] = ex[j] * inv_s; pm = fmaxf(pm, p[j]); }
        float e2[8], se2 = 0.0f;
        #pragma unroll
        for (int j = 0; j < 8; j++) { e2[j] = expf(p[j] - pm); se2 += e2[j]; }
        float Zf = se2 + 248.0f * expf(-pm);
        float invZ = 1.0f / Zf;
        float invd = 1.0f / (se2 * invZ + 1e-13f);
        float r[8];
        #pragma unroll
        for (int j = 0; j < 8; j++) r[j] = e2[j] * invZ * invd;

        int gn = graph_of(n);
        if (lane == gn) {
            #pragma unroll
            for (int j = 0; j < 8; j++) g_r[n * 8 + j] = r[j];
        }
        float rb[8];
        #pragma unroll
        for (int j = 0; j < 8; j++) rb[j] = __shfl_sync(0xFFFFFFFFu, r[j], gn);

        float4 ev = *reinterpret_cast<const float4*>(zr + lane * 4);
        int slot = gn - g0;
        float4* a4 = reinterpret_cast<float4*>(ac + slot * 1024) + lane;
        #pragma unroll
        for (int a = 0; a < 8; a++) {
            float ra = rb[a];
            float4 t = a4[a * 32];
            t.x = fmaf(ra, ev.x, t.x);
            t.y = fmaf(ra, ev.y, t.y);
            t.z = fmaf(ra, ev.z, t.z);
            t.w = fmaf(ra, ev.w, t.w);
            a4[a * 32] = t;
        }
    }
    __syncthreads();
    for (int idx = tid; idx < 2048; idx += 128) {
        float s = acc[0][idx] + acc[1][idx] + acc[2][idx] + acc[3][idx];
        int slot = idx >> 10, rest = idx & 1023, a = rest >> 7, c = rest & 127;
        int gg = g0 + slot;
        if (gg < NB && s != 0.0f)
            atomicAdd(out + H_OFF + ((gg << 3) + a) * 128 + c, s);
    }
}

// ---------------------------------------------------------------- per-edge adj: 8x8 outer products
__global__ __launch_bounds__(256) void k_adj(float* __restrict__ out) {
    __shared__ float acc[2 * 2048];
    int tid = threadIdx.x;
    for (int i = tid; i < 4096; i += 256) acc[i] = 0.0f;
    __syncthreads();
    int e0 = blockIdx.x * 2048;
    int g0 = graph_of(g_sorted[e0].y);
    int warp = tid >> 5, lane = tid & 31;
    int aL = lane >> 2;
    int b0 = (lane & 3) * 2;

    for (int i = 0; i < 256; i++) {
        int e = e0 + warp * 256 + i;
        if (e >= EE) break;
        int2 ed = g_sorted[e];
        float v = 0.0f;
        if (lane < 8)       v = g_r[ed.x * 8 + lane];
        else if (lane < 16) v = g_r[ed.y * 8 + (lane - 8)];
        float rs  = __shfl_sync(0xFFFFFFFFu, v, aL);
        float rd0 = __shfl_sync(0xFFFFFFFFu, v, 8 + b0);
        float rd1 = __shfl_sync(0xFFFFFFFFu, v, 8 + b0 + 1);
        int gs = graph_of(ed.x), gd = graph_of(ed.y);
        int slot = gd - g0;
        int row = (gs << 3) + aL;
        float v0 = rs * rd0, v1 = rs * rd1;
        if (slot >= 0 && slot < 2) {
            atomicAdd(&acc[slot * 2048 + row * 8 + b0],     v0);
            atomicAdd(&acc[slot * 2048 + row * 8 + b0 + 1], v1);
        } else {
            atomicAdd(out + row * 256 + (gd << 3) + b0,     v0);
            atomicAdd(out + row * 256 + (gd << 3) + b0 + 1, v1);
        }
    }
    __syncthreads();
    for (int idx = tid; idx < 4096; idx += 256) {
        float s = acc[idx];
        int slot = idx >> 11, rest = idx & 2047, row = rest >> 3, bc = rest & 7;
        int gg = g0 + slot;
        if (gg < NB && s != 0.0f)
            atomicAdd(out + row * 256 + (gg << 3) + bc, s);
    }
}

// ---------------------------------------------------------------- launch
extern "C" void kernel_launch(void* const* d_in, const int* in_sizes, int n_in,
                              void* d_out, int out_size) {
    const float* x  = (const float*)d_in[0];
    const int*   ei = (const int*)d_in[1];
    const float* We = (const float*)d_in[3];
    const float* be = (const float*)d_in[4];
    const float* Wp = (const float*)d_in[5];
    const float* bp = (const float*)d_in[6];
    float* out = (float*)d_out;

    static int smem_set = 0;
    if (!smem_set) {
        cudaFuncSetAttribute(k_gemm_mma, cudaFuncAttributeMaxDynamicSharedMemorySize,
                             SM_WORDS * 4);
        smem_set = 1;
    }

    const int init_total = OUT_ELEMS + WELEMS + XELEMS + EE;
    k_init<<<(init_total + 511) / 512, 512>>>(out, We, Wp, x, ei);
    k_scan1<<<49, 1024>>>();
    k_scan2<<<1, 64>>>();
    k_scan3<<<(NN + 255) / 256, 256>>>();
    k_scatter<<<(EE + 255) / 256, 256>>>(ei);
    k_neigh<<<(NN + 7) / 8, 256>>>(x);
    dim3 gg((NN + 127) / 128, 3);
    k_gemm_mma<<<gg, 256, SM_WORDS * 4>>>(be, bp);
    k_node<<<(NN + 127) / 128, 128>>>(out);
    k_adj<<<(EE + 2047) / 2048, 256>>>(out);
}

// round 9
// speedup vs baseline: 1.4909x; 1.0838x over previous
#include <cuda_runtime.h>

#define NN 50000
#define NN2 50176          // 196*256 padded rows
#define EE 800000
#define INF 128
#define NB 32
#define H_OFF 65536        // h starts after adj (256*256)
#define OUT_ELEMS 98304    // 256*256 + 256*128
#define WELEMS 98304       // 384*256 weight elements

__device__ __forceinline__ int graph_of(int n) { return (n * NB) / NN; }

// ---- scratch (module globals; zero-initialized, no runtime allocation) ----
__device__ float g_Z[(size_t)NN * 384];
__device__ float g_r[NN * 8];
__device__ int   g_counts[53248];      // zero at entry (static init; k_scan1 re-zeroes)
__device__ int   g_off[NN + 1];
__device__ int   g_cursor[NN];
__device__ int   g_bsum[64];
__device__ int2  g_sorted[EE];
__device__ float g_neigh[(size_t)NN2 * 128];   // fp32 mean-neighbor; pad rows stay 0
__device__ unsigned int g_BT[384 * 256];       // tf32 W^T: [n][k]

// ================= helpers =================
__device__ __forceinline__ unsigned int smem_u32(const void* p) {
    unsigned int a;
    asm("{ .reg .u64 t; cvta.to.shared.u64 t, %1; cvt.u32.u64 %0, t; }" : "=r"(a) : "l"(p));
    return a;
}
__device__ __forceinline__ unsigned int f2tf32(float v) {
    unsigned int o;
    asm("cvt.rna.tf32.f32 %0, %1;" : "=r"(o) : "f"(v));
    return o;
}
#define CP_ASYNC16(dst, src) \
    asm volatile("cp.async.ca.shared.global [%0], [%1], 16;" :: "r"(dst), "l"(src) : "memory")
#define CP_COMMIT()  asm volatile("cp.async.commit_group;" ::: "memory")
#define CP_WAIT1()   asm volatile("cp.async.wait_group 1;" ::: "memory")
#define CP_WAIT0()   asm volatile("cp.async.wait_group 0;" ::: "memory")

__device__ __forceinline__ void mma16n8k8(float* d, const unsigned* a, const unsigned* b) {
    asm volatile(
        "mma.sync.aligned.m16n8k8.row.col.f32.tf32.tf32.f32 "
        "{%0,%1,%2,%3}, {%4,%5,%6,%7}, {%8,%9}, {%0,%1,%2,%3};"
        : "+f"(d[0]), "+f"(d[1]), "+f"(d[2]), "+f"(d[3])
        : "r"(a[0]), "r"(a[1]), "r"(a[2]), "r"(a[3]), "r"(b[0]), "r"(b[1]));
}

// ---------------------------------------------------------------- init: zero out, W cvt, hist
__global__ void k_init(float* __restrict__ out,
                       const float* __restrict__ We, const float* __restrict__ Wp,
                       const int* __restrict__ ei) {
    int i = blockIdx.x * blockDim.x + threadIdx.x;
    if (i < OUT_ELEMS) {
        out[i] = 0.0f;
    } else if (i < OUT_ELEMS + WELEMS) {
        int idx = i - OUT_ELEMS;
        int k = idx & 255, n = idx >> 8;
        float v = (n < 128) ? We[k * 128 + n] : Wp[k * 256 + (n - 128)];
        g_BT[n * 256 + k] = f2tf32(v);
    } else if (i < OUT_ELEMS + WELEMS + EE) {
        int e = i - OUT_ELEMS - WELEMS;
        atomicAdd(&g_counts[ei[EE + e]], 1);
    }
}

// ---------------------------------------------------------------- scan stage 1
__global__ void k_scan1() {          // local excl scan + block total; re-zero counts
    int tid = threadIdx.x, lane = tid & 31, wid = tid >> 5;
    int idx = blockIdx.x * 1024 + tid;
    int v = (idx < NN) ? g_counts[idx] : 0;
    if (idx < NN) g_counts[idx] = 0;
    int s = v;
    #pragma unroll
    for (int o = 1; o < 32; o <<= 1) {
        int u = __shfl_up_sync(0xFFFFFFFFu, s, o);
        if (lane >= o) s += u;
    }
    __shared__ int ws[32];
    if (lane == 31) ws[wid] = s;
    __syncthreads();
    if (wid == 0) {
        int u = ws[lane];
        #pragma unroll
        for (int o = 1; o < 32; o <<= 1) {
            int q = __shfl_up_sync(0xFFFFFFFFu, u, o);
            if (lane >= o) u += q;
        }
        ws[lane] = u;
    }
    __syncthreads();
    int excl = s - v + (wid ? ws[wid - 1] : 0);
    if (idx < NN) g_off[idx] = excl;
    if (tid == 1023) g_bsum[blockIdx.x] = excl + v;
}

// ---------------------------------------------------------------- scan stages 2+3 merged
__global__ void k_scan23() {
    __shared__ int bo[64];
    __shared__ int w0s;
    int tid = threadIdx.x;
    int v = 0, s = 0;
    if (tid < 64) {
        v = (tid < 49) ? g_bsum[tid] : 0;
        s = v;
        #pragma unroll
        for (int o = 1; o < 32; o <<= 1) {
            int u = __shfl_up_sync(0xFFFFFFFFu, s, o);
            if ((tid & 31) >= o) s += u;
        }
        if (tid == 31) w0s = s;
    }
    __syncthreads();
    if (tid < 64) bo[tid] = s - v + ((tid >= 32) ? w0s : 0);
    __syncthreads();
    int idx = blockIdx.x * 256 + tid;
    if (idx < NN) {
        int val = g_off[idx] + bo[idx >> 10];
        g_off[idx] = val;
        g_cursor[idx] = val;
    }
    if (idx == 0) g_off[NN] = EE;
}

// ---------------------------------------------------------------- scatter into dst-sorted order
__global__ void k_scatter(const int* __restrict__ ei) {
    int e = blockIdx.x * 256 + threadIdx.x;
    if (e < EE) {
        int s = ei[e], d = ei[EE + e];
        int pos = atomicAdd(&g_cursor[d], 1);
        g_sorted[pos] = make_int2(s, d);
    }
}

// ---------------------------------------------------------------- mean aggregation -> fp32 g_neigh
__global__ void k_neigh(const float* __restrict__ x) {
    int node = blockIdx.x * 8 + (threadIdx.x >> 5);
    if (node >= NN) return;
    int lane = threadIdx.x & 31;
    int b = g_off[node], e = g_off[node + 1];
    float4 a0 = make_float4(0.f, 0.f, 0.f, 0.f);
    float4 a1 = make_float4(0.f, 0.f, 0.f, 0.f);
    float4 a2 = make_float4(0.f, 0.f, 0.f, 0.f);
    float4 a3 = make_float4(0.f, 0.f, 0.f, 0.f);
    int j = b;
    for (; j + 3 < e; j += 4) {
        int s0 = g_sorted[j].x, s1 = g_sorted[j + 1].x;
        int s2 = g_sorted[j + 2].x, s3 = g_sorted[j + 3].x;
        float4 v0 = *reinterpret_cast<const float4*>(x + (size_t)s0 * INF + lane * 4);
        float4 v1 = *reinterpret_cast<const float4*>(x + (size_t)s1 * INF + lane * 4);
        float4 v2 = *reinterpret_cast<const float4*>(x + (size_t)s2 * INF + lane * 4);
        float4 v3 = *reinterpret_cast<const float4*>(x + (size_t)s3 * INF + lane * 4);
        a0.x += v0.x; a0.y += v0.y; a0.z += v0.z; a0.w += v0.w;
        a1.x += v1.x; a1.y += v1.y; a1.z += v1.z; a1.w += v1.w;
        a2.x += v2.x; a2.y += v2.y; a2.z += v2.z; a2.w += v2.w;
        a3.x += v3.x; a3.y += v3.y; a3.z += v3.z; a3.w += v3.w;
    }
    for (; j < e; j++) {
        int s0 = g_sorted[j].x;
        float4 v0 = *reinterpret_cast<const float4*>(x + (size_t)s0 * INF + lane * 4);
        a0.x += v0.x; a0.y += v0.y; a0.z += v0.z; a0.w += v0.w;
    }
    float inv = 1.0f / (float)max(e - b, 1);
    float4 r;
    r.x = (a0.x + a1.x + a2.x + a3.x) * inv;
    r.y = (a0.y + a1.y + a2.y + a3.y) * inv;
    r.z = (a0.z + a1.z + a2.z + a3.z) * inv;
    r.w = (a0.w + a1.w + a2.w + a3.w) * inv;
    *reinterpret_cast<float4*>(g_neigh + (size_t)node * 128 + lane * 4) = r;
}

// ---------------------------------------------------------------- GEMM v3: 256x128 tiles
// K=256 in 8 chunks of 32, 3-stage cp.async, XOR swizzle. A read direct from x / g_neigh (RZ tf32).
// SMEM words: A stage s @ s*8192 (256 rows x 32); B stage s @ 24576 + s*4096. Total 36864 = 144KB.
#define SM_WORDS 36864
__global__ __launch_bounds__(256, 1) void k_gemm_mma(const float* __restrict__ x,
                                                     const float* __restrict__ be,
                                                     const float* __restrict__ bp) {
    extern __shared__ unsigned int sm[];
    int tid = threadIdx.x, lane = tid & 31, wid = tid >> 5;
    int warp_m = wid >> 1, warp_n = wid & 1;       // 4 x 2 warps, warp tile 64x64
    int g = lane >> 2, t = lane & 3;
    int m0 = blockIdx.x * 256, bt = blockIdx.y;
    const unsigned int* Bg = g_BT + (size_t)bt * 128 * 256;
    unsigned int sbase = smem_u32(sm);

    float acc[4][8][4];
    #pragma unroll
    for (int mt = 0; mt < 4; mt++)
        #pragma unroll
        for (int nt = 0; nt < 8; nt++)
            #pragma unroll
            for (int j = 0; j < 4; j++) acc[mt][nt][j] = 0.0f;

    auto load_chunk = [&](int c, int s) {
        unsigned int sa = sbase + (s * 8192) * 4;
        unsigned int sb = sbase + ((24576 + s * 4096)) * 4;
        // A: 256 rows x 32k  (2048 x 16B; 8 per thread)
        #pragma unroll
        for (int i = 0; i < 8; i++) {
            int e = tid + i * 256;             // 0..2047
            int m = e >> 3, ch = e & 7;
            unsigned int soff = (m * 32 + ((ch ^ (m & 7)) << 2)) * 4;
            const float* src;
            if (c < 4) {
                int row = m0 + m; if (row >= NN) row = NN - 1;
                src = x + (size_t)row * 128 + c * 32 + ch * 4;
            } else {
                src = g_neigh + (size_t)(m0 + m) * 128 + (c - 4) * 32 + ch * 4;
            }
            CP_ASYNC16(sa + soff, src);
        }
        // B: 128 rows x 32k  (1024 x 16B; 4 per thread)
        int k0 = c * 32;
        #pragma unroll
        for (int i = 0; i < 4; i++) {
            int e = tid + i * 256;
            int n = e >> 3, ch = e & 7;
            unsigned int soff = (n * 32 + ((ch ^ (n & 7)) << 2)) * 4;
            CP_ASYNC16(sb + soff, Bg + (size_t)n * 256 + k0 + ch * 4);
        }
    };
    auto compute = [&](int s) {
        const unsigned int* As = sm + s * 8192;
        const unsigned int* Bs = sm + 24576 + s * 4096;
        #pragma unroll
        for (int ks = 0; ks < 4; ks++) {
            int c0 = 2 * ks, c1 = 2 * ks + 1;
            unsigned int a[4][4], b[8][2];
            #pragma unroll
            for (int mt = 0; mt < 4; mt++) {
                int r0 = warp_m * 64 + mt * 16 + g;   // r0&7 == g
                int r1 = r0 + 8;
                a[mt][0] = As[r0 * 32 + ((c0 ^ g) << 2) + t];
                a[mt][1] = As[r1 * 32 + ((c0 ^ g) << 2) + t];
                a[mt][2] = As[r0 * 32 + ((c1 ^ g) << 2) + t];
                a[mt][3] = As[r1 * 32 + ((c1 ^ g) << 2) + t];
            }
            #pragma unroll
            for (int nt = 0; nt < 8; nt++) {
                int n = warp_n * 64 + nt * 8 + g;     // n&7 == g
                b[nt][0] = Bs[n * 32 + ((c0 ^ g) << 2) + t];
                b[nt][1] = Bs[n * 32 + ((c1 ^ g) << 2) + t];
            }
            #pragma unroll
            for (int mt = 0; mt < 4; mt++)
                #pragma unroll
                for (int nt = 0; nt < 8; nt++)
                    mma16n8k8(acc[mt][nt], a[mt], b[nt]);
        }
    };

    load_chunk(0, 0); CP_COMMIT();
    load_chunk(1, 1); CP_COMMIT();
    #pragma unroll
    for (int c = 0; c < 8; c++) {
        if (c < 7) { CP_WAIT1(); } else { CP_WAIT0(); }
        __syncthreads();
        compute(c % 3);
        if (c + 2 < 8) { load_chunk(c + 2, (c + 2) % 3); CP_COMMIT(); }
    }

    // ---- epilogue: bias + store ----
    __syncthreads();
    float* bsh = reinterpret_cast<float*>(sm);
    const float* bias = (bt == 0) ? be : bp + (bt - 1) * 128;
    if (tid < 128) bsh[tid] = bias[tid];
    __syncthreads();
    #pragma unroll
    for (int mt = 0; mt < 4; mt++) {
        int r0 = m0 + warp_m * 64 + mt * 16 + g;
        #pragma unroll
        for (int nt = 0; nt < 8; nt++) {
            int cloc = warp_n * 64 + nt * 8 + 2 * t;
            float bx = bsh[cloc], by = bsh[cloc + 1];
            if (r0 < NN) {
                float2 v = make_float2(acc[mt][nt][0] + bx, acc[mt][nt][1] + by);
                *reinterpret_cast<float2*>(g_Z + (size_t)r0 * 384 + bt * 128 + cloc) = v;
            }
            if (r0 + 8 < NN) {
                float2 v = make_float2(acc[mt][nt][2] + bx, acc[mt][nt][3] + by);
                *reinterpret_cast<float2*>(g_Z + (size_t)(r0 + 8) * 384 + bt * 128 + cloc) = v;
            }
        }
    }
}

// ---------------------------------------------------------------- per-node: softmax -> r, accumulate h
__global__ __launch_bounds__(128) void k_node(float* __restrict__ out) {
    __shared__ float acc[4][2048];
    int tid = threadIdx.x, warp = tid >> 5, lane = tid & 31;
    int n0 = blockIdx.x * 128;
    int g0 = graph_of(n0);
    for (int i = tid; i < 4 * 2048; i += 128) (&acc[0][0])[i] = 0.0f;
    __syncthreads();
    float* ac = acc[warp];

    for (int it = 0; it < 32; it++) {
        int n = n0 + warp * 32 + it;
        if (n >= NN) break;
        const float* zr = g_Z + (size_t)n * 384;
        float l[8];
        float4 q0 = *reinterpret_cast<const float4*>(zr + 128 + lane * 8);
        float4 q1 = *reinterpret_cast<const float4*>(zr + 128 + lane * 8 + 4);
        l[0] = q0.x; l[1] = q0.y; l[2] = q0.z; l[3] = q0.w;
        l[4] = q1.x; l[5] = q1.y; l[6] = q1.z; l[7] = q1.w;
        float mx = l[0];
        #pragma unroll
        for (int j = 1; j < 8; j++) mx = fmaxf(mx, l[j]);
        #pragma unroll
        for (int o = 16; o > 0; o >>= 1) mx = fmaxf(mx, __shfl_xor_sync(0xFFFFFFFFu, mx, o));
        float ex[8], s = 0.0f;
        #pragma unroll
        for (int j = 0; j < 8; j++) { ex[j] = expf(l[j] - mx); s += ex[j]; }
        #pragma unroll
        for (int o = 16; o > 0; o >>= 1) s += __shfl_xor_sync(0xFFFFFFFFu, s, o);
        float inv_s = 1.0f / s;
        float p[8], pm = -1e30f;
        #pragma unroll
        for (int j = 0; j < 8; j++) { p[j] = ex[j] * inv_s; pm = fmaxf(pm, p[j]); }
        float e2[8], se2 = 0.0f;
        #pragma unroll
        for (int j = 0; j < 8; j++) { e2[j] = expf(p[j] - pm); se2 += e2[j]; }
        float Zf = se2 + 248.0f * expf(-pm);
        float invZ = 1.0f / Zf;
        float invd = 1.0f / (se2 * invZ + 1e-13f);
        float r[8];
        #pragma unroll
        for (int j = 0; j < 8; j++) r[j] = e2[j] * invZ * invd;

        int gn = graph_of(n);
        if (lane == gn) {
            #pragma unroll
            for (int j = 0; j < 8; j++) g_r[n * 8 + j] = r[j];
        }
        float rb[8];
        #pragma unroll
        for (int j = 0; j < 8; j++) rb[j] = __shfl_sync(0xFFFFFFFFu, r[j], gn);

        float4 ev = *reinterpret_cast<const float4*>(zr + lane * 4);
        int slot = gn - g0;
        float4* a4 = reinterpret_cast<float4*>(ac + slot * 1024) + lane;
        #pragma unroll
        for (int a = 0; a < 8; a++) {
            float ra = rb[a];
            float4 t = a4[a * 32];
            t.x = fmaf(ra, ev.x, t.x);
            t.y = fmaf(ra, ev.y, t.y);
            t.z = fmaf(ra, ev.z, t.z);
            t.w = fmaf(ra, ev.w, t.w);
            a4[a * 32] = t;
        }
    }
    __syncthreads();
    for (int idx = tid; idx < 2048; idx += 128) {
        float s = acc[0][idx] + acc[1][idx] + acc[2][idx] + acc[3][idx];
        int slot = idx >> 10, rest = idx & 1023, a = rest >> 7, c = rest & 127;
        int gg = g0 + slot;
        if (gg < NB && s != 0.0f)
            atomicAdd(out + H_OFF + ((gg << 3) + a) * 128 + c, s);
    }
}

// ---------------------------------------------------------------- per-edge adj: 8x8 outer products
__global__ __launch_bounds__(256) void k_adj(float* __restrict__ out) {
    __shared__ float acc[2 * 2048];
    int tid = threadIdx.x;
    for (int i = tid; i < 4096; i += 256) acc[i] = 0.0f;
    __syncthreads();
    int e0 = blockIdx.x * 2048;
    int g0 = graph_of(g_sorted[e0].y);
    int warp = tid >> 5, lane = tid & 31;
    int aL = lane >> 2;
    int b0 = (lane & 3) * 2;

    for (int i = 0; i < 256; i++) {
        int e = e0 + warp * 256 + i;
        if (e >= EE) break;
        int2 ed = g_sorted[e];
        float v = 0.0f;
        if (lane < 8)       v = g_r[ed.x * 8 + lane];
        else if (lane < 16) v = g_r[ed.y * 8 + (lane - 8)];
        float rs  = __shfl_sync(0xFFFFFFFFu, v, aL);
        float rd0 = __shfl_sync(0xFFFFFFFFu, v, 8 + b0);
        float rd1 = __shfl_sync(0xFFFFFFFFu, v, 8 + b0 + 1);
        int gs = graph_of(ed.x), gd = graph_of(ed.y);
        int slot = gd - g0;
        int row = (gs << 3) + aL;
        float v0 = rs * rd0, v1 = rs * rd1;
        if (slot >= 0 && slot < 2) {
            atomicAdd(&acc[slot * 2048 + row * 8 + b0],     v0);
            atomicAdd(&acc[slot * 2048 + row * 8 + b0 + 1], v1);
        } else {
            atomicAdd(out + row * 256 + (gd << 3) + b0,     v0);
            atomicAdd(out + row * 256 + (gd << 3) + b0 + 1, v1);
        }
    }
    __syncthreads();
    for (int idx = tid; idx < 4096; idx += 256) {
        float s = acc[idx];
        int slot = idx >> 11, rest = idx & 2047, row = rest >> 3, bc = rest & 7;
        int gg = g0 + slot;
        if (gg < NB && s != 0.0f)
            atomicAdd(out + row * 256 + (gg << 3) + bc, s);
    }
}

// ---------------------------------------------------------------- launch
extern "C" void kernel_launch(void* const* d_in, const int* in_sizes, int n_in,
                              void* d_out, int out_size) {
    const float* x  = (const float*)d_in[0];
    const int*   ei = (const int*)d_in[1];
    const float* We = (const float*)d_in[3];
    const float* be = (const float*)d_in[4];
    const float* Wp = (const float*)d_in[5];
    const float* bp = (const float*)d_in[6];
    float* out = (float*)d_out;

    static int smem_set = 0;
    if (!smem_set) {
        cudaFuncSetAttribute(k_gemm_mma, cudaFuncAttributeMaxDynamicSharedMemorySize,
                             SM_WORDS * 4);
        smem_set = 1;
    }

    const int init_total = OUT_ELEMS + WELEMS + EE;
    k_init<<<(init_total + 511) / 512, 512>>>(out, We, Wp, ei);
    k_scan1<<<49, 1024>>>();
    k_scan23<<<(NN + 255) / 256, 256>>>();
    k_scatter<<<(EE + 255) / 256, 256>>>(ei);
    k_neigh<<<(NN + 7) / 8, 256>>>(x);
    dim3 gg(NN2 / 256, 3);
    k_gemm_mma<<<gg, 256, SM_WORDS * 4>>>(x, be, bp);
    k_node<<<(NN + 127) / 128, 128>>>(out);
    k_adj<<<(EE + 2047) / 2048, 256>>>(out);
}

// round 10
// speedup vs baseline: 1.5094x; 1.0124x over previous
#include <cuda_runtime.h>
#include <cuda_fp16.h>

#define NN 50000
#define NN2 50176          // 196*256 padded rows (pad stays zero)
#define EE 800000
#define INF 128
#define NB 32
#define H_OFF 65536        // h starts after adj (256*256)
#define OUT_ELEMS 98304    // 256*256 + 256*128
#define WELEMS 98304       // 384*256 weight elements
#define XELEMS (NN * INF)

__device__ __forceinline__ int graph_of(int n) { return (n * NB) / NN; }

// ---- scratch (module globals; zero-initialized, no runtime allocation) ----
__device__ float g_Z[(size_t)NN * 384];
__device__ float g_r[NN * 8];
__device__ int   g_counts[53248];      // zero at entry (static init; k_scan1 re-zeroes)
__device__ int   g_off[NN + 1];
__device__ int   g_cursor[NN];
__device__ int   g_bsum[64];
__device__ int2  g_sorted[EE];
__device__ __half g_Ah[(size_t)NN2 * 256];   // fp16 [x | neigh]; pad rows stay 0
__device__ __half g_Bh[384 * 256];           // fp16 W^T: [n][k]

// ================= helpers =================
__device__ __forceinline__ unsigned int smem_u32(const void* p) {
    unsigned int a;
    asm("{ .reg .u64 t; cvta.to.shared.u64 t, %1; cvt.u32.u64 %0, t; }" : "=r"(a) : "l"(p));
    return a;
}
#define CP_ASYNC16(dst, src) \
    asm volatile("cp.async.ca.shared.global [%0], [%1], 16;" :: "r"(dst), "l"(src) : "memory")
#define CP_COMMIT()  asm volatile("cp.async.commit_group;" ::: "memory")
#define CP_WAIT1()   asm volatile("cp.async.wait_group 1;" ::: "memory")
#define CP_WAIT0()   asm volatile("cp.async.wait_group 0;" ::: "memory")

__device__ __forceinline__ void ldmat4(unsigned* r, unsigned addr) {
    asm volatile("ldmatrix.sync.aligned.m8n8.x4.shared.b16 {%0,%1,%2,%3}, [%4];"
                 : "=r"(r[0]), "=r"(r[1]), "=r"(r[2]), "=r"(r[3]) : "r"(addr));
}
__device__ __forceinline__ void mma16n8k16(float* d, const unsigned* a, const unsigned* b) {
    asm volatile(
        "mma.sync.aligned.m16n8k16.row.col.f32.f16.f16.f32 "
        "{%0,%1,%2,%3}, {%4,%5,%6,%7}, {%8,%9}, {%0,%1,%2,%3};"
        : "+f"(d[0]), "+f"(d[1]), "+f"(d[2]), "+f"(d[3])
        : "r"(a[0]), "r"(a[1]), "r"(a[2]), "r"(a[3]), "r"(b[0]), "r"(b[1]));
}

// ---------------------------------------------------------------- init: zero out, W->fp16, x->fp16, hist
__global__ void k_init(float* __restrict__ out,
                       const float* __restrict__ We, const float* __restrict__ Wp,
                       const float* __restrict__ x, const int* __restrict__ ei) {
    int i = blockIdx.x * blockDim.x + threadIdx.x;
    if (i < OUT_ELEMS) {
        out[i] = 0.0f;
    } else if (i < OUT_ELEMS + WELEMS) {
        int idx = i - OUT_ELEMS;
        int k = idx & 255, n = idx >> 8;
        float v = (n < 128) ? We[k * 128 + n] : Wp[k * 256 + (n - 128)];
        g_Bh[n * 256 + k] = __float2half_rn(v);
    } else if (i < OUT_ELEMS + WELEMS + XELEMS) {
        int idx = i - OUT_ELEMS - WELEMS;
        int row = idx >> 7, col = idx & 127;
        g_Ah[(size_t)row * 256 + col] = __float2half_rn(x[idx]);
    } else if (i < OUT_ELEMS + WELEMS + XELEMS + EE) {
        int e = i - OUT_ELEMS - WELEMS - XELEMS;
        atomicAdd(&g_counts[ei[EE + e]], 1);
    }
}

// ---------------------------------------------------------------- scan stage 1
__global__ void k_scan1() {
    int tid = threadIdx.x, lane = tid & 31, wid = tid >> 5;
    int idx = blockIdx.x * 1024 + tid;
    int v = (idx < NN) ? g_counts[idx] : 0;
    if (idx < NN) g_counts[idx] = 0;
    int s = v;
    #pragma unroll
    for (int o = 1; o < 32; o <<= 1) {
        int u = __shfl_up_sync(0xFFFFFFFFu, s, o);
        if (lane >= o) s += u;
    }
    __shared__ int ws[32];
    if (lane == 31) ws[wid] = s;
    __syncthreads();
    if (wid == 0) {
        int u = ws[lane];
        #pragma unroll
        for (int o = 1; o < 32; o <<= 1) {
            int q = __shfl_up_sync(0xFFFFFFFFu, u, o);
            if (lane >= o) u += q;
        }
        ws[lane] = u;
    }
    __syncthreads();
    int excl = s - v + (wid ? ws[wid - 1] : 0);
    if (idx < NN) g_off[idx] = excl;
    if (tid == 1023) g_bsum[blockIdx.x] = excl + v;
}

// ---------------------------------------------------------------- scan stages 2+3 merged
__global__ void k_scan23() {
    __shared__ int bo[64];
    __shared__ int w0s;
    int tid = threadIdx.x;
    int v = 0, s = 0;
    if (tid < 64) {
        v = (tid < 49) ? g_bsum[tid] : 0;
        s = v;
        #pragma unroll
        for (int o = 1; o < 32; o <<= 1) {
            int u = __shfl_up_sync(0xFFFFFFFFu, s, o);
            if ((tid & 31) >= o) s += u;
        }
        if (tid == 31) w0s = s;
    }
    __syncthreads();
    if (tid < 64) bo[tid] = s - v + ((tid >= 32) ? w0s : 0);
    __syncthreads();
    int idx = blockIdx.x * 256 + tid;
    if (idx < NN) {
        int val = g_off[idx] + bo[idx >> 10];
        g_off[idx] = val;
        g_cursor[idx] = val;
    }
    if (idx == 0) g_off[NN] = EE;
}

// ---------------------------------------------------------------- scatter into dst-sorted order
__global__ void k_scatter(const int* __restrict__ ei) {
    int e = blockIdx.x * 256 + threadIdx.x;
    if (e < EE) {
        int s = ei[e], d = ei[EE + e];
        int pos = atomicAdd(&g_cursor[d], 1);
        g_sorted[pos] = make_int2(s, d);
    }
}

// ---------------------------------------------------------------- mean aggregation -> fp16 cols 128..255
__global__ void k_neigh(const float* __restrict__ x) {
    int node = blockIdx.x * 8 + (threadIdx.x >> 5);
    if (node >= NN) return;
    int lane = threadIdx.x & 31;
    int b = g_off[node], e = g_off[node + 1];
    float4 a0 = make_float4(0.f, 0.f, 0.f, 0.f);
    float4 a1 = make_float4(0.f, 0.f, 0.f, 0.f);
    float4 a2 = make_float4(0.f, 0.f, 0.f, 0.f);
    float4 a3 = make_float4(0.f, 0.f, 0.f, 0.f);
    int j = b;
    for (; j + 3 < e; j += 4) {
        int s0 = g_sorted[j].x, s1 = g_sorted[j + 1].x;
        int s2 = g_sorted[j + 2].x, s3 = g_sorted[j + 3].x;
        float4 v0 = *reinterpret_cast<const float4*>(x + (size_t)s0 * INF + lane * 4);
        float4 v1 = *reinterpret_cast<const float4*>(x + (size_t)s1 * INF + lane * 4);
        float4 v2 = *reinterpret_cast<const float4*>(x + (size_t)s2 * INF + lane * 4);
        float4 v3 = *reinterpret_cast<const float4*>(x + (size_t)s3 * INF + lane * 4);
        a0.x += v0.x; a0.y += v0.y; a0.z += v0.z; a0.w += v0.w;
        a1.x += v1.x; a1.y += v1.y; a1.z += v1.z; a1.w += v1.w;
        a2.x += v2.x; a2.y += v2.y; a2.z += v2.z; a2.w += v2.w;
        a3.x += v3.x; a3.y += v3.y; a3.z += v3.z; a3.w += v3.w;
    }
    for (; j < e; j++) {
        int s0 = g_sorted[j].x;
        float4 v0 = *reinterpret_cast<const float4*>(x + (size_t)s0 * INF + lane * 4);
        a0.x += v0.x; a0.y += v0.y; a0.z += v0.z; a0.w += v0.w;
    }
    float inv = 1.0f / (float)max(e - b, 1);
    __half2 h0 = __floats2half2_rn((a0.x + a1.x + a2.x + a3.x) * inv,
                                   (a0.y + a1.y + a2.y + a3.y) * inv);
    __half2 h1 = __floats2half2_rn((a0.z + a1.z + a2.z + a3.z) * inv,
                                   (a0.w + a1.w + a2.w + a3.w) * inv);
    uint2 o;
    o.x = *reinterpret_cast<unsigned*>(&h0);
    o.y = *reinterpret_cast<unsigned*>(&h1);
    *reinterpret_cast<uint2*>(g_Ah + (size_t)node * 256 + 128 + lane * 4) = o;
}

// ---------------------------------------------------------------- GEMM v4: fp16 m16n8k16 + ldmatrix
// CTA 256x128, K=256 in 8 chunks of 32 halves, 3-stage cp.async.
// SMEM: A stage s @ byte s*16384 (256 rows x 64B, chunk^((row>>1)&3)); B stage s @ 49152 + s*8192.
// Total 72KB.
#define SM_WORDS 18432
__global__ __launch_bounds__(256, 1) void k_gemm_mma(const float* __restrict__ be,
                                                     const float* __restrict__ bp) {
    extern __shared__ unsigned int sm[];
    int tid = threadIdx.x, lane = tid & 31, wid = tid >> 5;
    int warp_m = wid >> 1, warp_n = wid & 1;       // 4 x 2 warps, warp tile 64x64
    int g = lane >> 2, t = lane & 3;
    int m0 = blockIdx.x * 256, bt = blockIdx.y;
    unsigned int sbase = smem_u32(sm);

    float acc[4][8][4];
    #pragma unroll
    for (int mt = 0; mt < 4; mt++)
        #pragma unroll
        for (int nt = 0; nt < 8; nt++)
            #pragma unroll
            for (int j = 0; j < 4; j++) acc[mt][nt][j] = 0.0f;

    auto load_chunk = [&](int c, int s) {
        unsigned int sa = sbase + s * 16384;
        unsigned int sb = sbase + 49152 + s * 8192;
        // A: 256 rows x 4 chunks of 16B = 1024 tasks, 4/thread
        #pragma unroll
        for (int i = 0; i < 4; i++) {
            int e = tid + i * 256;
            int row = e >> 2, ch = e & 3;
            unsigned int soff = row * 64 + ((ch ^ ((row >> 1) & 3)) << 4);
            CP_ASYNC16(sa + soff, g_Ah + (size_t)(m0 + row) * 256 + c * 32 + ch * 8);
        }
        // B: 128 rows x 4 chunks = 512 tasks, 2/thread
        #pragma unroll
        for (int i = 0; i < 2; i++) {
            int e = tid + i * 256;
            int n = e >> 2, ch = e & 3;
            unsigned int soff = n * 64 + ((ch ^ ((n >> 1) & 3)) << 4);
            CP_ASYNC16(sb + soff, g_Bh + (size_t)(bt * 128 + n) * 256 + c * 32 + ch * 8);
        }
    };
    auto compute = [&](int s) {
        unsigned int Ab = sbase + s * 16384;
        unsigned int Bb = sbase + 49152 + s * 8192;
        #pragma unroll
        for (int ks = 0; ks < 2; ks++) {
            unsigned a[4][4], b[4][4];
            #pragma unroll
            for (int mt = 0; mt < 4; mt++) {
                int row = warp_m * 64 + mt * 16 + ((lane >> 3) & 1) * 8 + (lane & 7);
                int ch = 2 * ks + (lane >> 4);
                ldmat4(a[mt], Ab + row * 64 + ((ch ^ ((row >> 1) & 3)) << 4));
            }
            #pragma unroll
            for (int np = 0; np < 4; np++) {
                int n = warp_n * 64 + np * 16 + ((lane >> 4) << 3) + (lane & 7);
                int ch = 2 * ks + ((lane >> 3) & 1);
                ldmat4(b[np], Bb + n * 64 + ((ch ^ ((n >> 1) & 3)) << 4));
            }
            #pragma unroll
            for (int mt = 0; mt < 4; mt++)
                #pragma unroll
                for (int np = 0; np < 4; np++) {
                    mma16n8k16(acc[mt][2 * np],     a[mt], b[np]);
                    mma16n8k16(acc[mt][2 * np + 1], a[mt], b[np] + 2);
                }
        }
    };

    load_chunk(0, 0); CP_COMMIT();
    load_chunk(1, 1); CP_COMMIT();
    #pragma unroll
    for (int c = 0; c < 8; c++) {
        if (c < 7) { CP_WAIT1(); } else { CP_WAIT0(); }
        __syncthreads();
        compute(c % 3);
        if (c + 2 < 8) { load_chunk(c + 2, (c + 2) % 3); CP_COMMIT(); }
    }

    // ---- epilogue: bias + store ----
    __syncthreads();
    float* bsh = reinterpret_cast<float*>(sm);
    const float* bias = (bt == 0) ? be : bp + (bt - 1) * 128;
    if (tid < 128) bsh[tid] = bias[tid];
    __syncthreads();
    #pragma unroll
    for (int mt = 0; mt < 4; mt++) {
        int r0 = m0 + warp_m * 64 + mt * 16 + g;
        #pragma unroll
        for (int nt = 0; nt < 8; nt++) {
            int cloc = warp_n * 64 + nt * 8 + 2 * t;
            float bx = bsh[cloc], by = bsh[cloc + 1];
            if (r0 < NN) {
                float2 v = make_float2(acc[mt][nt][0] + bx, acc[mt][nt][1] + by);
                *reinterpret_cast<float2*>(g_Z + (size_t)r0 * 384 + bt * 128 + cloc) = v;
            }
            if (r0 + 8 < NN) {
                float2 v = make_float2(acc[mt][nt][2] + bx, acc[mt][nt][3] + by);
                *reinterpret_cast<float2*>(g_Z + (size_t)(r0 + 8) * 384 + bt * 128 + cloc) = v;
            }
        }
    }
}

// ---------------------------------------------------------------- per-node: softmax -> r, accumulate h
__global__ __launch_bounds__(128) void k_node(float* __restrict__ out) {
    __shared__ float acc[4][2048];
    int tid = threadIdx.x, warp = tid >> 5, lane = tid & 31;
    int n0 = blockIdx.x * 128;
    int g0 = graph_of(n0);
    for (int i = tid; i < 4 * 2048; i += 128) (&acc[0][0])[i] = 0.0f;
    __syncthreads();
    float* ac = acc[warp];

    for (int it = 0; it < 32; it++) {
        int n = n0 + warp * 32 + it;
        if (n >= NN) break;
        const float* zr = g_Z + (size_t)n * 384;
        float l[8];
        float4 q0 = *reinterpret_cast<const float4*>(zr + 128 + lane * 8);
        float4 q1 = *reinterpret_cast<const float4*>(zr + 128 + lane * 8 + 4);
        l[0] = q0.x; l[1] = q0.y; l[2] = q0.z; l[3] = q0.w;
        l[4] = q1.x; l[5] = q1.y; l[6] = q1.z; l[7] = q1.w;
        float mx = l[0];
        #pragma unroll
        for (int j = 1; j < 8; j++) mx = fmaxf(mx, l[j]);
        #pragma unroll
        for (int o = 16; o > 0; o >>= 1) mx = fmaxf(mx, __shfl_xor_sync(0xFFFFFFFFu, mx, o));
        float ex[8], s = 0.0f;
        #pragma unroll
        for (int j = 0; j < 8; j++) { ex[j] = expf(l[j] - mx); s += ex[j]; }
        #pragma unroll
        for (int o = 16; o > 0; o >>= 1) s += __shfl_xor_sync(0xFFFFFFFFu, s, o);
        float inv_s = 1.0f / s;
        float p[8], pm = -1e30f;
        #pragma unroll
        for (int j = 0; j < 8; j++) { p[j] = ex[j] * inv_s; pm = fmaxf(pm, p[j]); }
        float e2[8], se2 = 0.0f;
        #pragma unroll
        for (int j = 0; j < 8; j++) { e2[j] = expf(p[j] - pm); se2 += e2[j]; }
        float Zf = se2 + 248.0f * expf(-pm);
        float invZ = 1.0f / Zf;
        float invd = 1.0f / (se2 * invZ + 1e-13f);
        float r[8];
        #pragma unroll
        for (int j = 0; j < 8; j++) r[j] = e2[j] * invZ * invd;

        int gn = graph_of(n);
        if (lane == gn) {
            #pragma unroll
            for (int j = 0; j < 8; j++) g_r[n * 8 + j] = r[j];
        }
        float rb[8];
        #pragma unroll
        for (int j = 0; j < 8; j++) rb[j] = __shfl_sync(0xFFFFFFFFu, r[j], gn);

        float4 ev = *reinterpret_cast<const float4*>(zr + lane * 4);
        int slot = gn - g0;
        float4* a4 = reinterpret_cast<float4*>(ac + slot * 1024) + lane;
        #pragma unroll
        for (int a = 0; a < 8; a++) {
            float ra = rb[a];
            float4 t = a4[a * 32];
            t.x = fmaf(ra, ev.x, t.x);
            t.y = fmaf(ra, ev.y, t.y);
            t.z = fmaf(ra, ev.z, t.z);
            t.w = fmaf(ra, ev.w, t.w);
            a4[a * 32] = t;
        }
    }
    __syncthreads();
    for (int idx = tid; idx < 2048; idx += 128) {
        float s = acc[0][idx] + acc[1][idx] + acc[2][idx] + acc[3][idx];
        int slot = idx >> 10, rest = idx & 1023, a = rest >> 7, c = rest & 127;
        int gg = g0 + slot;
        if (gg < NB && s != 0.0f)
            atomicAdd(out + H_OFF + ((gg << 3) + a) * 128 + c, s);
    }
}

// ---------------------------------------------------------------- per-edge adj: 8x8 outer products
__global__ __launch_bounds__(256) void k_adj(float* __restrict__ out) {
    __shared__ float acc[2 * 2048];
    int tid = threadIdx.x;
    for (int i = tid; i < 4096; i += 256) acc[i] = 0.0f;
    __syncthreads();
    int e0 = blockIdx.x * 2048;
    int g0 = graph_of(g_sorted[e0].y);
    int warp = tid >> 5, lane = tid & 31;
    int aL = lane >> 2;
    int b0 = (lane & 3) * 2;

    for (int i = 0; i < 256; i++) {
        int e = e0 + warp * 256 + i;
        if (e >= EE) break;
        int2 ed = g_sorted[e];
        float v = 0.0f;
        if (lane < 8)       v = g_r[ed.x * 8 + lane];
        else if (lane < 16) v = g_r[ed.y * 8 + (lane - 8)];
        float rs  = __shfl_sync(0xFFFFFFFFu, v, aL);
        float rd0 = __shfl_sync(0xFFFFFFFFu, v, 8 + b0);
        float rd1 = __shfl_sync(0xFFFFFFFFu, v, 8 + b0 + 1);
        int gs = graph_of(ed.x), gd = graph_of(ed.y);
        int slot = gd - g0;
        int row = (gs << 3) + aL;
        float v0 = rs * rd0, v1 = rs * rd1;
        if (slot >= 0 && slot < 2) {
            atomicAdd(&acc[slot * 2048 + row * 8 + b0],     v0);
            atomicAdd(&acc[slot * 2048 + row * 8 + b0 + 1], v1);
        } else {
            atomicAdd(out + row * 256 + (gd << 3) + b0,     v0);
            atomicAdd(out + row * 256 + (gd << 3) + b0 + 1, v1);
        }
    }
    __syncthreads();
    for (int idx = tid; idx < 4096; idx += 256) {
        float s = acc[idx];
        int slot = idx >> 11, rest = idx & 2047, row = rest >> 3, bc = rest & 7;
        int gg = g0 + slot;
        if (gg < NB && s != 0.0f)
            atomicAdd(out + row * 256 + (gg << 3) + bc, s);
    }
}

// ---------------------------------------------------------------- launch
extern "C" void kernel_launch(void* const* d_in, const int* in_sizes, int n_in,
                              void* d_out, int out_size) {
    const float* x  = (const float*)d_in[0];
    const int*   ei = (const int*)d_in[1];
    const float* We = (const float*)d_in[3];
    const float* be = (const float*)d_in[4];
    const float* Wp = (const float*)d_in[5];
    const float* bp = (const float*)d_in[6];
    float* out = (float*)d_out;

    static int smem_set = 0;
    if (!smem_set) {
        cudaFuncSetAttribute(k_gemm_mma, cudaFuncAttributeMaxDynamicSharedMemorySize,
                             SM_WORDS * 4);
        smem_set = 1;
    }

    const int init_total = OUT_ELEMS + WELEMS + XELEMS + EE;
    k_init<<<(init_total + 511) / 512, 512>>>(out, We, Wp, x, ei);
    k_scan1<<<49, 1024>>>();
    k_scan23<<<(NN + 255) / 256, 256>>>();
    k_scatter<<<(EE + 255) / 256, 256>>>(ei);
    k_neigh<<<(NN + 7) / 8, 256>>>(x);
    dim3 gg(NN2 / 256, 3);
    k_gemm_mma<<<gg, 256, SM_WORDS * 4>>>(be, bp);
    k_node<<<(NN + 127) / 128, 128>>>(out);
    k_adj<<<(EE + 2047) / 2048, 256>>>(out);
}

// round 11
// speedup vs baseline: 1.8111x; 1.1999x over previous
#include <cuda_runtime.h>
#include <cuda_fp16.h>

#define NN 50000
#define NN2 50176          // 196*256 padded rows (pad stays zero)
#define EE 800000
#define INF 128
#define NB 32
#define H_OFF 65536        // h starts after adj (256*256)
#define OUT_ELEMS 98304    // 256*256 + 256*128
#define WELEMS 98304       // 384*256 weight elements
#define XELEMS (NN * INF)

__device__ __forceinline__ int graph_of(int n) { return (n * NB) / NN; }

// ---- scratch (module globals; zero-initialized, no runtime allocation) ----
__device__ float g_Z[(size_t)NN * 384];
__device__ float g_r[NN * 8];
__device__ int   g_counts[53248];      // zero at entry (static init; k_scan1 re-zeroes)
__device__ int   g_off[NN + 1];
__device__ int   g_cursor[NN];
__device__ int   g_bsum[64];
__device__ int2  g_sorted[EE];
__device__ __half g_Ah[(size_t)NN2 * 256];   // fp16 [x | neigh]; pad rows stay 0
__device__ __half g_Bh[384 * 256];           // fp16 W^T: [n][k]

// ================= helpers =================
__device__ __forceinline__ unsigned int smem_u32(const void* p) {
    unsigned int a;
    asm("{ .reg .u64 t; cvta.to.shared.u64 t, %1; cvt.u32.u64 %0, t; }" : "=r"(a) : "l"(p));
    return a;
}
#define CP_ASYNC16(dst, src) \
    asm volatile("cp.async.ca.shared.global [%0], [%1], 16;" :: "r"(dst), "l"(src) : "memory")
#define CP_COMMIT()  asm volatile("cp.async.commit_group;" ::: "memory")
#define CP_WAIT1()   asm volatile("cp.async.wait_group 1;" ::: "memory")
#define CP_WAIT0()   asm volatile("cp.async.wait_group 0;" ::: "memory")

__device__ __forceinline__ void ldmat4(unsigned* r, unsigned addr) {
    asm volatile("ldmatrix.sync.aligned.m8n8.x4.shared.b16 {%0,%1,%2,%3}, [%4];"
                 : "=r"(r[0]), "=r"(r[1]), "=r"(r[2]), "=r"(r[3]) : "r"(addr));
}
__device__ __forceinline__ void mma16n8k16(float* d, const unsigned* a, const unsigned* b) {
    asm volatile(
        "mma.sync.aligned.m16n8k16.row.col.f32.f16.f16.f32 "
        "{%0,%1,%2,%3}, {%4,%5,%6,%7}, {%8,%9}, {%0,%1,%2,%3};"
        : "+f"(d[0]), "+f"(d[1]), "+f"(d[2]), "+f"(d[3])
        : "r"(a[0]), "r"(a[1]), "r"(a[2]), "r"(a[3]), "r"(b[0]), "r"(b[1]));
}

// ---------------------------------------------------------------- init: zero out, W->fp16, x->fp16, hist
__global__ void k_init(float* __restrict__ out,
                       const float* __restrict__ We, const float* __restrict__ Wp,
                       const float* __restrict__ x, const int* __restrict__ ei) {
    int i = blockIdx.x * blockDim.x + threadIdx.x;
    if (i < OUT_ELEMS) {
        out[i] = 0.0f;
    } else if (i < OUT_ELEMS + WELEMS) {
        int idx = i - OUT_ELEMS;
        int k = idx & 255, n = idx >> 8;
        float v = (n < 128) ? We[k * 128 + n] : Wp[k * 256 + (n - 128)];
        g_Bh[n * 256 + k] = __float2half_rn(v);
    } else if (i < OUT_ELEMS + WELEMS + XELEMS) {
        int idx = i - OUT_ELEMS - WELEMS;
        int row = idx >> 7, col = idx & 127;
        g_Ah[(size_t)row * 256 + col] = __float2half_rn(x[idx]);
    } else if (i < OUT_ELEMS + WELEMS + XELEMS + EE) {
        int e = i - OUT_ELEMS - WELEMS - XELEMS;
        atomicAdd(&g_counts[ei[EE + e]], 1);
    }
}

// ---------------------------------------------------------------- scan stage 1
__global__ void k_scan1() {
    int tid = threadIdx.x, lane = tid & 31, wid = tid >> 5;
    int idx = blockIdx.x * 1024 + tid;
    int v = (idx < NN) ? g_counts[idx] : 0;
    if (idx < NN) g_counts[idx] = 0;
    int s = v;
    #pragma unroll
    for (int o = 1; o < 32; o <<= 1) {
        int u = __shfl_up_sync(0xFFFFFFFFu, s, o);
        if (lane >= o) s += u;
    }
    __shared__ int ws[32];
    if (lane == 31) ws[wid] = s;
    __syncthreads();
    if (wid == 0) {
        int u = ws[lane];
        #pragma unroll
        for (int o = 1; o < 32; o <<= 1) {
            int q = __shfl_up_sync(0xFFFFFFFFu, u, o);
            if (lane >= o) u += q;
        }
        ws[lane] = u;
    }
    __syncthreads();
    int excl = s - v + (wid ? ws[wid - 1] : 0);
    if (idx < NN) g_off[idx] = excl;
    if (tid == 1023) g_bsum[blockIdx.x] = excl + v;
}

// ---------------------------------------------------------------- scan stages 2+3 merged
__global__ void k_scan23() {
    __shared__ int bo[64];
    __shared__ int w0s;
    int tid = threadIdx.x;
    int v = 0, s = 0;
    if (tid < 64) {
        v = (tid < 49) ? g_bsum[tid] : 0;
        s = v;
        #pragma unroll
        for (int o = 1; o < 32; o <<= 1) {
            int u = __shfl_up_sync(0xFFFFFFFFu, s, o);
            if ((tid & 31) >= o) s += u;
        }
        if (tid == 31) w0s = s;
    }
    __syncthreads();
    if (tid < 64) bo[tid] = s - v + ((tid >= 32) ? w0s : 0);
    __syncthreads();
    int idx = blockIdx.x * 256 + tid;
    if (idx < NN) {
        int val = g_off[idx] + bo[idx >> 10];
        g_off[idx] = val;
        g_cursor[idx] = val;
    }
    if (idx == 0) g_off[NN] = EE;
}

// ---------------------------------------------------------------- scatter into dst-sorted order
__global__ void k_scatter(const int* __restrict__ ei) {
    int e = blockIdx.x * 256 + threadIdx.x;
    if (e < EE) {
        int s = ei[e], d = ei[EE + e];
        int pos = atomicAdd(&g_cursor[d], 1);
        g_sorted[pos] = make_int2(s, d);
    }
}

// ---------------------------------------------------------------- mean aggregation (fp16 reads) -> fp16 cols 128..255
__global__ void k_neigh() {
    int node = blockIdx.x * 8 + (threadIdx.x >> 5);
    if (node >= NN) return;
    int lane = threadIdx.x & 31;
    int b = g_off[node], e = g_off[node + 1];
    float2 a0 = make_float2(0.f, 0.f), b0 = make_float2(0.f, 0.f);
    float2 a1 = make_float2(0.f, 0.f), b1 = make_float2(0.f, 0.f);
    float2 a2 = make_float2(0.f, 0.f), b2 = make_float2(0.f, 0.f);
    float2 a3 = make_float2(0.f, 0.f), b3 = make_float2(0.f, 0.f);
    int j = b;
    for (; j + 3 < e; j += 4) {
        int s0 = g_sorted[j].x, s1 = g_sorted[j + 1].x;
        int s2 = g_sorted[j + 2].x, s3 = g_sorted[j + 3].x;
        uint2 u0 = *reinterpret_cast<const uint2*>(g_Ah + (size_t)s0 * 256 + lane * 4);
        uint2 u1 = *reinterpret_cast<const uint2*>(g_Ah + (size_t)s1 * 256 + lane * 4);
        uint2 u2 = *reinterpret_cast<const uint2*>(g_Ah + (size_t)s2 * 256 + lane * 4);
        uint2 u3 = *reinterpret_cast<const uint2*>(g_Ah + (size_t)s3 * 256 + lane * 4);
        float2 f;
        f = __half22float2(*reinterpret_cast<__half2*>(&u0.x)); a0.x += f.x; a0.y += f.y;
        f = __half22float2(*reinterpret_cast<__half2*>(&u0.y)); b0.x += f.x; b0.y += f.y;
        f = __half22float2(*reinterpret_cast<__half2*>(&u1.x)); a1.x += f.x; a1.y += f.y;
        f = __half22float2(*reinterpret_cast<__half2*>(&u1.y)); b1.x += f.x; b1.y += f.y;
        f = __half22float2(*reinterpret_cast<__half2*>(&u2.x)); a2.x += f.x; a2.y += f.y;
        f = __half22float2(*reinterpret_cast<__half2*>(&u2.y)); b2.x += f.x; b2.y += f.y;
        f = __half22float2(*reinterpret_cast<__half2*>(&u3.x)); a3.x += f.x; a3.y += f.y;
        f = __half22float2(*reinterpret_cast<__half2*>(&u3.y)); b3.x += f.x; b3.y += f.y;
    }
    for (; j < e; j++) {
        int s0 = g_sorted[j].x;
        uint2 u0 = *reinterpret_cast<const uint2*>(g_Ah + (size_t)s0 * 256 + lane * 4);
        float2 f;
        f = __half22float2(*reinterpret_cast<__half2*>(&u0.x)); a0.x += f.x; a0.y += f.y;
        f = __half22float2(*reinterpret_cast<__half2*>(&u0.y)); b0.x += f.x; b0.y += f.y;
    }
    float inv = 1.0f / (float)max(e - b, 1);
    __half2 h0 = __floats2half2_rn((a0.x + a1.x + a2.x + a3.x) * inv,
                                   (a0.y + a1.y + a2.y + a3.y) * inv);
    __half2 h1 = __floats2half2_rn((b0.x + b1.x + b2.x + b3.x) * inv,
                                   (b0.y + b1.y + b2.y + b3.y) * inv);
    uint2 o;
    o.x = *reinterpret_cast<unsigned*>(&h0);
    o.y = *reinterpret_cast<unsigned*>(&h1);
    *reinterpret_cast<uint2*>(g_Ah + (size_t)node * 256 + 128 + lane * 4) = o;
}

// ---------------------------------------------------------------- GEMM v4: fp16 m16n8k16 + ldmatrix
// CTA 256x128, K=256 in 8 chunks of 32 halves, 3-stage cp.async. SMEM 72KB.
#define SM_WORDS 18432
__global__ __launch_bounds__(256, 1) void k_gemm_mma(const float* __restrict__ be,
                                                     const float* __restrict__ bp) {
    extern __shared__ unsigned int sm[];
    int tid = threadIdx.x, lane = tid & 31, wid = tid >> 5;
    int warp_m = wid >> 1, warp_n = wid & 1;       // 4 x 2 warps, warp tile 64x64
    int g = lane >> 2, t = lane & 3;
    int m0 = blockIdx.x * 256, bt = blockIdx.y;
    unsigned int sbase = smem_u32(sm);

    float acc[4][8][4];
    #pragma unroll
    for (int mt = 0; mt < 4; mt++)
        #pragma unroll
        for (int nt = 0; nt < 8; nt++)
            #pragma unroll
            for (int j = 0; j < 4; j++) acc[mt][nt][j] = 0.0f;

    auto load_chunk = [&](int c, int s) {
        unsigned int sa = sbase + s * 16384;
        unsigned int sb = sbase + 49152 + s * 8192;
        #pragma unroll
        for (int i = 0; i < 4; i++) {
            int e = tid + i * 256;
            int row = e >> 2, ch = e & 3;
            unsigned int soff = row * 64 + ((ch ^ ((row >> 1) & 3)) << 4);
            CP_ASYNC16(sa + soff, g_Ah + (size_t)(m0 + row) * 256 + c * 32 + ch * 8);
        }
        #pragma unroll
        for (int i = 0; i < 2; i++) {
            int e = tid + i * 256;
            int n = e >> 2, ch = e & 3;
            unsigned int soff = n * 64 + ((ch ^ ((n >> 1) & 3)) << 4);
            CP_ASYNC16(sb + soff, g_Bh + (size_t)(bt * 128 + n) * 256 + c * 32 + ch * 8);
        }
    };
    auto compute = [&](int s) {
        unsigned int Ab = sbase + s * 16384;
        unsigned int Bb = sbase + 49152 + s * 8192;
        #pragma unroll
        for (int ks = 0; ks < 2; ks++) {
            unsigned a[4][4], b[4][4];
            #pragma unroll
            for (int mt = 0; mt < 4; mt++) {
                int row = warp_m * 64 + mt * 16 + ((lane >> 3) & 1) * 8 + (lane & 7);
                int ch = 2 * ks + (lane >> 4);
                ldmat4(a[mt], Ab + row * 64 + ((ch ^ ((row >> 1) & 3)) << 4));
            }
            #pragma unroll
            for (int np = 0; np < 4; np++) {
                int n = warp_n * 64 + np * 16 + ((lane >> 4) << 3) + (lane & 7);
                int ch = 2 * ks + ((lane >> 3) & 1);
                ldmat4(b[np], Bb + n * 64 + ((ch ^ ((n >> 1) & 3)) << 4));
            }
            #pragma unroll
            for (int mt = 0; mt < 4; mt++)
                #pragma unroll
                for (int np = 0; np < 4; np++) {
                    mma16n8k16(acc[mt][2 * np],     a[mt], b[np]);
                    mma16n8k16(acc[mt][2 * np + 1], a[mt], b[np] + 2);
                }
        }
    };

    load_chunk(0, 0); CP_COMMIT();
    load_chunk(1, 1); CP_COMMIT();
    #pragma unroll
    for (int c = 0; c < 8; c++) {
        if (c < 7) { CP_WAIT1(); } else { CP_WAIT0(); }
        __syncthreads();
        compute(c % 3);
        if (c + 2 < 8) { load_chunk(c + 2, (c + 2) % 3); CP_COMMIT(); }
    }

    // ---- epilogue: bias + store ----
    __syncthreads();
    float* bsh = reinterpret_cast<float*>(sm);
    const float* bias = (bt == 0) ? be : bp + (bt - 1) * 128;
    if (tid < 128) bsh[tid] = bias[tid];
    __syncthreads();
    #pragma unroll
    for (int mt = 0; mt < 4; mt++) {
        int r0 = m0 + warp_m * 64 + mt * 16 + g;
        #pragma unroll
        for (int nt = 0; nt < 8; nt++) {
            int cloc = warp_n * 64 + nt * 8 + 2 * t;
            float bx = bsh[cloc], by = bsh[cloc + 1];
            if (r0 < NN) {
                float2 v = make_float2(acc[mt][nt][0] + bx, acc[mt][nt][1] + by);
                *reinterpret_cast<float2*>(g_Z + (size_t)r0 * 384 + bt * 128 + cloc) = v;
            }
            if (r0 + 8 < NN) {
                float2 v = make_float2(acc[mt][nt][2] + bx, acc[mt][nt][3] + by);
                *reinterpret_cast<float2*>(g_Z + (size_t)(r0 + 8) * 384 + bt * 128 + cloc) = v;
            }
        }
    }
}

// ---------------------------------------------------------------- per-node: softmax -> r, accumulate h (prefetched)
__global__ __launch_bounds__(128) void k_node(float* __restrict__ out) {
    __shared__ float acc[4][2048];
    int tid = threadIdx.x, warp = tid >> 5, lane = tid & 31;
    int n0 = blockIdx.x * 128;
    int g0 = graph_of(n0);
    for (int i = tid; i < 4 * 2048; i += 128) (&acc[0][0])[i] = 0.0f;
    __syncthreads();
    float* ac = acc[warp];

    int nfirst = n0 + warp * 32;
    float4 q0, q1, ev;
    if (nfirst < NN) {
        const float* zr = g_Z + (size_t)nfirst * 384;
        q0 = *reinterpret_cast<const float4*>(zr + 128 + lane * 8);
        q1 = *reinterpret_cast<const float4*>(zr + 128 + lane * 8 + 4);
        ev = *reinterpret_cast<const float4*>(zr + lane * 4);
    }
    for (int it = 0; it < 32; it++) {
        int n = nfirst + it;
        if (n >= NN) break;
        float4 c0 = q0, c1 = q1, cev = ev;
        if (it < 31 && n + 1 < NN) {            // prefetch next row
            const float* zr = g_Z + (size_t)(n + 1) * 384;
            q0 = *reinterpret_cast<const float4*>(zr + 128 + lane * 8);
            q1 = *reinterpret_cast<const float4*>(zr + 128 + lane * 8 + 4);
            ev = *reinterpret_cast<const float4*>(zr + lane * 4);
        }
        float l[8];
        l[0] = c0.x; l[1] = c0.y; l[2] = c0.z; l[3] = c0.w;
        l[4] = c1.x; l[5] = c1.y; l[6] = c1.z; l[7] = c1.w;
        float mx = l[0];
        #pragma unroll
        for (int j = 1; j < 8; j++) mx = fmaxf(mx, l[j]);
        #pragma unroll
        for (int o = 16; o > 0; o >>= 1) mx = fmaxf(mx, __shfl_xor_sync(0xFFFFFFFFu, mx, o));
        float ex[8], s = 0.0f;
        #pragma unroll
        for (int j = 0; j < 8; j++) { ex[j] = expf(l[j] - mx); s += ex[j]; }
        #pragma unroll
        for (int o = 16; o > 0; o >>= 1) s += __shfl_xor_sync(0xFFFFFFFFu, s, o);
        float inv_s = 1.0f / s;
        float p[8], pm = -1e30f;
        #pragma unroll
        for (int j = 0; j < 8; j++) { p[j] = ex[j] * inv_s; pm = fmaxf(pm, p[j]); }
        float e2[8], se2 = 0.0f;
        #pragma unroll
        for (int j = 0; j < 8; j++) { e2[j] = expf(p[j] - pm); se2 += e2[j]; }
        float Zf = se2 + 248.0f * expf(-pm);
        float invZ = 1.0f / Zf;
        float invd = 1.0f / (se2 * invZ + 1e-13f);
        float r[8];
        #pragma unroll
        for (int j = 0; j < 8; j++) r[j] = e2[j] * invZ * invd;

        int gn = graph_of(n);
        if (lane == gn) {
            #pragma unroll
            for (int j = 0; j < 8; j++) g_r[n * 8 + j] = r[j];
        }
        float rb[8];
        #pragma unroll
        for (int j = 0; j < 8; j++) rb[j] = __shfl_sync(0xFFFFFFFFu, r[j], gn);

        int slot = gn - g0;
        float4* a4 = reinterpret_cast<float4*>(ac + slot * 1024) + lane;
        #pragma unroll
        for (int a = 0; a < 8; a++) {
            float ra = rb[a];
            float4 t = a4[a * 32];
            t.x = fmaf(ra, cev.x, t.x);
            t.y = fmaf(ra, cev.y, t.y);
            t.z = fmaf(ra, cev.z, t.z);
            t.w = fmaf(ra, cev.w, t.w);
            a4[a * 32] = t;
        }
    }
    __syncthreads();
    for (int idx = tid; idx < 2048; idx += 128) {
        float s = acc[0][idx] + acc[1][idx] + acc[2][idx] + acc[3][idx];
        int slot = idx >> 10, rest = idx & 1023, a = rest >> 7, c = rest & 127;
        int gg = g0 + slot;
        if (gg < NB && s != 0.0f)
            atomicAdd(out + H_OFF + ((gg << 3) + a) * 128 + c, s);
    }
}

// ---------------------------------------------------------------- per-edge adj: 2 edges per warp-iter
__global__ __launch_bounds__(256) void k_adj(float* __restrict__ out) {
    __shared__ float acc[2 * 2048];
    int tid = threadIdx.x;
    for (int i = tid; i < 4096; i += 256) acc[i] = 0.0f;
    __syncthreads();
    int e0 = blockIdx.x * 2048;
    int g0 = graph_of(g_sorted[e0].y);
    int warp = tid >> 5, lane = tid & 31;
    int aL = lane >> 2;
    int b0 = (lane & 3) * 2;

    for (int i = 0; i < 128; i++) {
        int e = e0 + warp * 256 + i * 2;
        if (e >= EE) break;
        int2 edA = g_sorted[e];
        bool hasB = (e + 1 < EE);
        int2 edB = hasB ? g_sorted[e + 1] : edA;
        float v = 0.0f;
        if (lane < 8)       v = g_r[edA.x * 8 + lane];
        else if (lane < 16) v = g_r[edA.y * 8 + (lane - 8)];
        else if (lane < 24) v = g_r[edB.x * 8 + (lane - 16)];
        else                v = g_r[edB.y * 8 + (lane - 24)];
        float rsA  = __shfl_sync(0xFFFFFFFFu, v, aL);
        float rdA0 = __shfl_sync(0xFFFFFFFFu, v, 8 + b0);
        float rdA1 = __shfl_sync(0xFFFFFFFFu, v, 8 + b0 + 1);
        float rsB  = __shfl_sync(0xFFFFFFFFu, v, 16 + aL);
        float rdB0 = __shfl_sync(0xFFFFFFFFu, v, 24 + b0);
        float rdB1 = __shfl_sync(0xFFFFFFFFu, v, 24 + b0 + 1);
        {
            int gs = graph_of(edA.x), gd = graph_of(edA.y);
            int slot = gd - g0;
            int row = (gs << 3) + aL;
            float v0 = rsA * rdA0, v1 = rsA * rdA1;
            if (slot >= 0 && slot < 2) {
                atomicAdd(&acc[slot * 2048 + row * 8 + b0],     v0);
                atomicAdd(&acc[slot * 2048 + row * 8 + b0 + 1], v1);
            } else {
                atomicAdd(out + row * 256 + (gd << 3) + b0,     v0);
                atomicAdd(out + row * 256 + (gd << 3) + b0 + 1, v1);
            }
        }
        if (hasB) {
            int gs = graph_of(edB.x), gd = graph_of(edB.y);
            int slot = gd - g0;
            int row = (gs << 3) + aL;
            float v0 = rsB * rdB0, v1 = rsB * rdB1;
            if (slot >= 0 && slot < 2) {
                atomicAdd(&acc[slot * 2048 + row * 8 + b0],     v0);
                atomicAdd(&acc[slot * 2048 + row * 8 + b0 + 1], v1);
            } else {
                atomicAdd(out + row * 256 + (gd << 3) + b0,     v0);
                atomicAdd(out + row * 256 + (gd << 3) + b0 + 1, v1);
            }
        }
    }
    __syncthreads();
    for (int idx = tid; idx < 4096; idx += 256) {
        float s = acc[idx];
        int slot = idx >> 11, rest = idx & 2047, row = rest >> 3, bc = rest & 7;
        int gg = g0 + slot;
        if (gg < NB && s != 0.0f)
            atomicAdd(out + row * 256 + (gg << 3) + bc, s);
    }
}

// ---------------------------------------------------------------- launch
extern "C" void kernel_launch(void* const* d_in, const int* in_sizes, int n_in,
                              void* d_out, int out_size) {
    const float* x  = (const float*)d_in[0];
    const int*   ei = (const int*)d_in[1];
    const float* We = (const float*)d_in[3];
    const float* be = (const float*)d_in[4];
    const float* Wp = (const float*)d_in[5];
    const float* bp = (const float*)d_in[6];
    float* out = (float*)d_out;

    static int smem_set = 0;
    if (!smem_set) {
        cudaFuncSetAttribute(k_gemm_mma, cudaFuncAttributeMaxDynamicSharedMemorySize,
                             SM_WORDS * 4);
        smem_set = 1;
    }

    const int init_total = OUT_ELEMS + WELEMS + XELEMS + EE;
    k_init<<<(init_total + 511) / 512, 512>>>(out, We, Wp, x, ei);
    k_scan1<<<49, 1024>>>();
    k_scan23<<<(NN + 255) / 256, 256>>>();
    k_scatter<<<(EE + 255) / 256, 256>>>(ei);
    k_neigh<<<(NN + 7) / 8, 256>>>();
    dim3 gg(NN2 / 256, 3);
    k_gemm_mma<<<gg, 256, SM_WORDS * 4>>>(be, bp);
    k_node<<<(NN + 127) / 128, 128>>>(out);
    k_adj<<<(EE + 2047) / 2048, 256>>>(out);
}

// round 12
// speedup vs baseline: 1.8932x; 1.0453x over previous
#include <cuda_runtime.h>
#include <cuda_fp16.h>

#define NN 50000
#define NN2 50176          // 196*256 padded rows (pad stays zero)
#define EE 800000
#define INF 128
#define NB 32
#define H_OFF 65536        // h starts after adj (256*256)
#define OUT_ELEMS 98304    // 256*256 + 256*128
#define WELEMS 98304       // 384*256 weight elements
#define XELEMS (NN * INF)

__device__ __forceinline__ int graph_of(int n) { return (n * NB) / NN; }

// ---- scratch (module globals; zero-initialized, no runtime allocation) ----
__device__ float g_Z[(size_t)NN * 384];
__device__ float g_r[NN * 8];
__device__ int   g_counts[53248];      // zero at entry (static init; k_scan1 re-zeroes)
__device__ int   g_off[NN + 1];
__device__ int   g_cursor[NN];
__device__ int   g_bsum[64];
__device__ int2  g_sorted[EE];
__device__ __half g_Ah[(size_t)NN2 * 256];   // fp16 [x | neigh]; pad rows stay 0
__device__ __half g_Bh[384 * 256];           // fp16 W^T: [n][k]

// ================= helpers =================
__device__ __forceinline__ unsigned int smem_u32(const void* p) {
    unsigned int a;
    asm("{ .reg .u64 t; cvta.to.shared.u64 t, %1; cvt.u32.u64 %0, t; }" : "=r"(a) : "l"(p));
    return a;
}
#define CP_ASYNC16(dst, src) \
    asm volatile("cp.async.ca.shared.global [%0], [%1], 16;" :: "r"(dst), "l"(src) : "memory")
#define CP_COMMIT()  asm volatile("cp.async.commit_group;" ::: "memory")
#define CP_WAIT1()   asm volatile("cp.async.wait_group 1;" ::: "memory")
#define CP_WAIT0()   asm volatile("cp.async.wait_group 0;" ::: "memory")

__device__ __forceinline__ void ldmat4(unsigned* r, unsigned addr) {
    asm volatile("ldmatrix.sync.aligned.m8n8.x4.shared.b16 {%0,%1,%2,%3}, [%4];"
                 : "=r"(r[0]), "=r"(r[1]), "=r"(r[2]), "=r"(r[3]) : "r"(addr));
}
__device__ __forceinline__ void mma16n8k16(float* d, const unsigned* a, const unsigned* b) {
    asm volatile(
        "mma.sync.aligned.m16n8k16.row.col.f32.f16.f16.f32 "
        "{%0,%1,%2,%3}, {%4,%5,%6,%7}, {%8,%9}, {%0,%1,%2,%3};"
        : "+f"(d[0]), "+f"(d[1]), "+f"(d[2]), "+f"(d[3])
        : "r"(a[0]), "r"(a[1]), "r"(a[2]), "r"(a[3]), "r"(b[0]), "r"(b[1]));
}

// ---------------------------------------------------------------- init: zero out, W->fp16, x->fp16, hist
__global__ void k_init(float* __restrict__ out,
                       const float* __restrict__ We, const float* __restrict__ Wp,
                       const float* __restrict__ x, const int* __restrict__ ei) {
    int i = blockIdx.x * blockDim.x + threadIdx.x;
    if (i < OUT_ELEMS) {
        out[i] = 0.0f;
    } else if (i < OUT_ELEMS + WELEMS) {
        int idx = i - OUT_ELEMS;
        int k = idx & 255, n = idx >> 8;
        float v = (n < 128) ? We[k * 128 + n] : Wp[k * 256 + (n - 128)];
        g_Bh[n * 256 + k] = __float2half_rn(v);
    } else if (i < OUT_ELEMS + WELEMS + XELEMS) {
        int idx = i - OUT_ELEMS - WELEMS;
        int row = idx >> 7, col = idx & 127;
        g_Ah[(size_t)row * 256 + col] = __float2half_rn(x[idx]);
    } else if (i < OUT_ELEMS + WELEMS + XELEMS + EE) {
        int e = i - OUT_ELEMS - WELEMS - XELEMS;
        atomicAdd(&g_counts[ei[EE + e]], 1);
    }
}

// ---------------------------------------------------------------- scan stage 1
__global__ void k_scan1() {
    int tid = threadIdx.x, lane = tid & 31, wid = tid >> 5;
    int idx = blockIdx.x * 1024 + tid;
    int v = (idx < NN) ? g_counts[idx] : 0;
    if (idx < NN) g_counts[idx] = 0;
    int s = v;
    #pragma unroll
    for (int o = 1; o < 32; o <<= 1) {
        int u = __shfl_up_sync(0xFFFFFFFFu, s, o);
        if (lane >= o) s += u;
    }
    __shared__ int ws[32];
    if (lane == 31) ws[wid] = s;
    __syncthreads();
    if (wid == 0) {
        int u = ws[lane];
        #pragma unroll
        for (int o = 1; o < 32; o <<= 1) {
            int q = __shfl_up_sync(0xFFFFFFFFu, u, o);
            if (lane >= o) u += q;
        }
        ws[lane] = u;
    }
    __syncthreads();
    int excl = s - v + (wid ? ws[wid - 1] : 0);
    if (idx < NN) g_off[idx] = excl;
    if (tid == 1023) g_bsum[blockIdx.x] = excl + v;
}

// ---------------------------------------------------------------- scan stages 2+3 merged
__global__ void k_scan23() {
    __shared__ int bo[64];
    __shared__ int w0s;
    int tid = threadIdx.x;
    int v = 0, s = 0;
    if (tid < 64) {
        v = (tid < 49) ? g_bsum[tid] : 0;
        s = v;
        #pragma unroll
        for (int o = 1; o < 32; o <<= 1) {
            int u = __shfl_up_sync(0xFFFFFFFFu, s, o);
            if ((tid & 31) >= o) s += u;
        }
        if (tid == 31) w0s = s;
    }
    __syncthreads();
    if (tid < 64) bo[tid] = s - v + ((tid >= 32) ? w0s : 0);
    __syncthreads();
    int idx = blockIdx.x * 256 + tid;
    if (idx < NN) {
        int val = g_off[idx] + bo[idx >> 10];
        g_off[idx] = val;
        g_cursor[idx] = val;
    }
    if (idx == 0) g_off[NN] = EE;
}

// ---------------------------------------------------------------- scatter: 2 edges per thread
__global__ void k_scatter(const int* __restrict__ ei) {
    int e = (blockIdx.x * 256 + threadIdx.x) * 2;
    if (e < EE) {
        int2 sv = *reinterpret_cast<const int2*>(ei + e);
        int2 dv = *reinterpret_cast<const int2*>(ei + EE + e);
        int p0 = atomicAdd(&g_cursor[dv.x], 1);
        g_sorted[p0] = make_int2(sv.x, dv.x);
        int p1 = atomicAdd(&g_cursor[dv.y], 1);
        g_sorted[p1] = make_int2(sv.y, dv.y);
    }
}

// ---------------------------------------------------------------- mean aggregation (fp16 reads, MLP 8)
__global__ void k_neigh() {
    int node = blockIdx.x * 8 + (threadIdx.x >> 5);
    if (node >= NN) return;
    int lane = threadIdx.x & 31;
    int b = g_off[node], e = g_off[node + 1];
    float2 aa[8], bb[8];
    #pragma unroll
    for (int i = 0; i < 8; i++) { aa[i] = make_float2(0.f, 0.f); bb[i] = make_float2(0.f, 0.f); }
    int j = b;
    for (; j + 7 < e; j += 8) {
        uint2 u[8];
        #pragma unroll
        for (int i = 0; i < 8; i++) {
            int s0 = g_sorted[j + i].x;
            u[i] = *reinterpret_cast<const uint2*>(g_Ah + (size_t)s0 * 256 + lane * 4);
        }
        #pragma unroll
        for (int i = 0; i < 8; i++) {
            float2 f0 = __half22float2(*reinterpret_cast<__half2*>(&u[i].x));
            float2 f1 = __half22float2(*reinterpret_cast<__half2*>(&u[i].y));
            aa[i].x += f0.x; aa[i].y += f0.y;
            bb[i].x += f1.x; bb[i].y += f1.y;
        }
    }
    for (; j < e; j++) {
        int s0 = g_sorted[j].x;
        uint2 u0 = *reinterpret_cast<const uint2*>(g_Ah + (size_t)s0 * 256 + lane * 4);
        float2 f0 = __half22float2(*reinterpret_cast<__half2*>(&u0.x));
        float2 f1 = __half22float2(*reinterpret_cast<__half2*>(&u0.y));
        aa[0].x += f0.x; aa[0].y += f0.y;
        bb[0].x += f1.x; bb[0].y += f1.y;
    }
    float2 sa = make_float2(0.f, 0.f), sb = make_float2(0.f, 0.f);
    #pragma unroll
    for (int i = 0; i < 8; i++) {
        sa.x += aa[i].x; sa.y += aa[i].y;
        sb.x += bb[i].x; sb.y += bb[i].y;
    }
    float inv = 1.0f / (float)max(e - b, 1);
    __half2 h0 = __floats2half2_rn(sa.x * inv, sa.y * inv);
    __half2 h1 = __floats2half2_rn(sb.x * inv, sb.y * inv);
    uint2 o;
    o.x = *reinterpret_cast<unsigned*>(&h0);
    o.y = *reinterpret_cast<unsigned*>(&h1);
    *reinterpret_cast<uint2*>(g_Ah + (size_t)node * 256 + 128 + lane * 4) = o;
}

// ---------------------------------------------------------------- GEMM v4: fp16 m16n8k16 + ldmatrix
// CTA 256x128, K=256 in 8 chunks of 32 halves, 3-stage cp.async. SMEM 72KB.
#define SM_WORDS 18432
__global__ __launch_bounds__(256, 1) void k_gemm_mma(const float* __restrict__ be,
                                                     const float* __restrict__ bp) {
    extern __shared__ unsigned int sm[];
    int tid = threadIdx.x, lane = tid & 31, wid = tid >> 5;
    int warp_m = wid >> 1, warp_n = wid & 1;       // 4 x 2 warps, warp tile 64x64
    int g = lane >> 2, t = lane & 3;
    int m0 = blockIdx.x * 256, bt = blockIdx.y;
    unsigned int sbase = smem_u32(sm);

    float acc[4][8][4];
    #pragma unroll
    for (int mt = 0; mt < 4; mt++)
        #pragma unroll
        for (int nt = 0; nt < 8; nt++)
            #pragma unroll
            for (int j = 0; j < 4; j++) acc[mt][nt][j] = 0.0f;

    auto load_chunk = [&](int c, int s) {
        unsigned int sa = sbase + s * 16384;
        unsigned int sb = sbase + 49152 + s * 8192;
        #pragma unroll
        for (int i = 0; i < 4; i++) {
            int e = tid + i * 256;
            int row = e >> 2, ch = e & 3;
            unsigned int soff = row * 64 + ((ch ^ ((row >> 1) & 3)) << 4);
            CP_ASYNC16(sa + soff, g_Ah + (size_t)(m0 + row) * 256 + c * 32 + ch * 8);
        }
        #pragma unroll
        for (int i = 0; i < 2; i++) {
            int e = tid + i * 256;
            int n = e >> 2, ch = e & 3;
            unsigned int soff = n * 64 + ((ch ^ ((n >> 1) & 3)) << 4);
            CP_ASYNC16(sb + soff, g_Bh + (size_t)(bt * 128 + n) * 256 + c * 32 + ch * 8);
        }
    };
    auto compute = [&](int s) {
        unsigned int Ab = sbase + s * 16384;
        unsigned int Bb = sbase + 49152 + s * 8192;
        #pragma unroll
        for (int ks = 0; ks < 2; ks++) {
            unsigned a[4][4], b[4][4];
            #pragma unroll
            for (int mt = 0; mt < 4; mt++) {
                int row = warp_m * 64 + mt * 16 + ((lane >> 3) & 1) * 8 + (lane & 7);
                int ch = 2 * ks + (lane >> 4);
                ldmat4(a[mt], Ab + row * 64 + ((ch ^ ((row >> 1) & 3)) << 4));
            }
            #pragma unroll
            for (int np = 0; np < 4; np++) {
                int n = warp_n * 64 + np * 16 + ((lane >> 4) << 3) + (lane & 7);
                int ch = 2 * ks + ((lane >> 3) & 1);
                ldmat4(b[np], Bb + n * 64 + ((ch ^ ((n >> 1) & 3)) << 4));
            }
            #pragma unroll
            for (int mt = 0; mt < 4; mt++)
                #pragma unroll
                for (int np = 0; np < 4; np++) {
                    mma16n8k16(acc[mt][2 * np],     a[mt], b[np]);
                    mma16n8k16(acc[mt][2 * np + 1], a[mt], b[np] + 2);
                }
        }
    };

    load_chunk(0, 0); CP_COMMIT();
    load_chunk(1, 1); CP_COMMIT();
    #pragma unroll
    for (int c = 0; c < 8; c++) {
        if (c < 7) { CP_WAIT1(); } else { CP_WAIT0(); }
        __syncthreads();
        compute(c % 3);
        if (c + 2 < 8) { load_chunk(c + 2, (c + 2) % 3); CP_COMMIT(); }
    }

    // ---- epilogue: bias + store ----
    __syncthreads();
    float* bsh = reinterpret_cast<float*>(sm);
    const float* bias = (bt == 0) ? be : bp + (bt - 1) * 128;
    if (tid < 128) bsh[tid] = bias[tid];
    __syncthreads();
    #pragma unroll
    for (int mt = 0; mt < 4; mt++) {
        int r0 = m0 + warp_m * 64 + mt * 16 + g;
        #pragma unroll
        for (int nt = 0; nt < 8; nt++) {
            int cloc = warp_n * 64 + nt * 8 + 2 * t;
            float bx = bsh[cloc], by = bsh[cloc + 1];
            if (r0 < NN) {
                float2 v = make_float2(acc[mt][nt][0] + bx, acc[mt][nt][1] + by);
                *reinterpret_cast<float2*>(g_Z + (size_t)r0 * 384 + bt * 128 + cloc) = v;
            }
            if (r0 + 8 < NN) {
                float2 v = make_float2(acc[mt][nt][2] + bx, acc[mt][nt][3] + by);
                *reinterpret_cast<float2*>(g_Z + (size_t)(r0 + 8) * 384 + bt * 128 + cloc) = v;
            }
        }
    }
}

// ---------------------------------------------------------------- per-node: softmax -> r, accumulate h (prefetched)
__global__ __launch_bounds__(128) void k_node(float* __restrict__ out) {
    __shared__ float acc[4][2048];
    int tid = threadIdx.x, warp = tid >> 5, lane = tid & 31;
    int n0 = blockIdx.x * 128;
    int g0 = graph_of(n0);
    for (int i = tid; i < 4 * 2048; i += 128) (&acc[0][0])[i] = 0.0f;
    __syncthreads();
    float* ac = acc[warp];

    int nfirst = n0 + warp * 32;
    float4 q0, q1, ev;
    if (nfirst < NN) {
        const float* zr = g_Z + (size_t)nfirst * 384;
        q0 = *reinterpret_cast<const float4*>(zr + 128 + lane * 8);
        q1 = *reinterpret_cast<const float4*>(zr + 128 + lane * 8 + 4);
        ev = *reinterpret_cast<const float4*>(zr + lane * 4);
    }
    for (int it = 0; it < 32; it++) {
        int n = nfirst + it;
        if (n >= NN) break;
        float4 c0 = q0, c1 = q1, cev = ev;
        if (it < 31 && n + 1 < NN) {            // prefetch next row
            const float* zr = g_Z + (size_t)(n + 1) * 384;
            q0 = *reinterpret_cast<const float4*>(zr + 128 + lane * 8);
            q1 = *reinterpret_cast<const float4*>(zr + 128 + lane * 8 + 4);
            ev = *reinterpret_cast<const float4*>(zr + lane * 4);
        }
        float l[8];
        l[0] = c0.x; l[1] = c0.y; l[2] = c0.z; l[3] = c0.w;
        l[4] = c1.x; l[5] = c1.y; l[6] = c1.z; l[7] = c1.w;
        float mx = l[0];
        #pragma unroll
        for (int j = 1; j < 8; j++) mx = fmaxf(mx, l[j]);
        #pragma unroll
        for (int o = 16; o > 0; o >>= 1) mx = fmaxf(mx, __shfl_xor_sync(0xFFFFFFFFu, mx, o));
        float ex[8], s = 0.0f;
        #pragma unroll
        for (int j = 0; j < 8; j++) { ex[j] = expf(l[j] - mx); s += ex[j]; }
        #pragma unroll
        for (int o = 16; o > 0; o >>= 1) s += __shfl_xor_sync(0xFFFFFFFFu, s, o);
        float inv_s = 1.0f / s;
        float p[8], pm = -1e30f;
        #pragma unroll
        for (int j = 0; j < 8; j++) { p[j] = ex[j] * inv_s; pm = fmaxf(pm, p[j]); }
        float e2[8], se2 = 0.0f;
        #pragma unroll
        for (int j = 0; j < 8; j++) { e2[j] = expf(p[j] - pm); se2 += e2[j]; }
        float Zf = se2 + 248.0f * expf(-pm);
        float invZ = 1.0f / Zf;
        float invd = 1.0f / (se2 * invZ + 1e-13f);
        float r[8];
        #pragma unroll
        for (int j = 0; j < 8; j++) r[j] = e2[j] * invZ * invd;

        int gn = graph_of(n);
        if (lane == gn) {
            #pragma unroll
            for (int j = 0; j < 8; j++) g_r[n * 8 + j] = r[j];
        }
        float rb[8];
        #pragma unroll
        for (int j = 0; j < 8; j++) rb[j] = __shfl_sync(0xFFFFFFFFu, r[j], gn);

        int slot = gn - g0;
        float4* a4 = reinterpret_cast<float4*>(ac + slot * 1024) + lane;
        #pragma unroll
        for (int a = 0; a < 8; a++) {
            float ra = rb[a];
            float4 t = a4[a * 32];
            t.x = fmaf(ra, cev.x, t.x);
            t.y = fmaf(ra, cev.y, t.y);
            t.z = fmaf(ra, cev.z, t.z);
            t.w = fmaf(ra, cev.w, t.w);
            a4[a * 32] = t;
        }
    }
    __syncthreads();
    for (int idx = tid; idx < 2048; idx += 128) {
        float s = acc[0][idx] + acc[1][idx] + acc[2][idx] + acc[3][idx];
        int slot = idx >> 10, rest = idx & 1023, a = rest >> 7, c = rest & 127;
        int gg = g0 + slot;
        if (gg < NB && s != 0.0f)
            atomicAdd(out + H_OFF + ((gg << 3) + a) * 128 + c, s);
    }
}

// ---------------------------------------------------------------- per-edge adj: 4 edges per warp-iter
__global__ __launch_bounds__(256) void k_adj(float* __restrict__ out) {
    __shared__ float acc[2 * 2048];
    int tid = threadIdx.x;
    for (int i = tid; i < 4096; i += 256) acc[i] = 0.0f;
    __syncthreads();
    int e0 = blockIdx.x * 2048;
    int g0 = graph_of(g_sorted[e0].y);
    int warp = tid >> 5, lane = tid & 31;
    int aL = lane >> 2;
    int b0 = (lane & 3) * 2;
    int sel = lane >> 3;          // 0..3
    int li = lane & 7;

    for (int i = 0; i < 64; i++) {
        int e = e0 + warp * 256 + i * 4;
        if (e >= EE) break;
        int4 p0 = *reinterpret_cast<const int4*>(&g_sorted[e]);      // edges e, e+1
        int4 p1 = *reinterpret_cast<const int4*>(&g_sorted[e + 2]);  // edges e+2, e+3
        int idx1 = (sel == 0) ? p0.x : (sel == 1) ? p0.y : (sel == 2) ? p0.z : p0.w;
        int idx2 = (sel == 0) ? p1.x : (sel == 1) ? p1.y : (sel == 2) ? p1.z : p1.w;
        float v1 = g_r[idx1 * 8 + li];
        float v2 = g_r[idx2 * 8 + li];
        int src[4] = {p0.x, p0.z, p1.x, p1.z};
        int dst[4] = {p0.y, p0.w, p1.y, p1.w};
        float rs[4], rd0[4], rd1[4];
        rs[0]  = __shfl_sync(0xFFFFFFFFu, v1, aL);
        rd0[0] = __shfl_sync(0xFFFFFFFFu, v1, 8 + b0);
        rd1[0] = __shfl_sync(0xFFFFFFFFu, v1, 8 + b0 + 1);
        rs[1]  = __shfl_sync(0xFFFFFFFFu, v1, 16 + aL);
        rd0[1] = __shfl_sync(0xFFFFFFFFu, v1, 24 + b0);
        rd1[1] = __shfl_sync(0xFFFFFFFFu, v1, 24 + b0 + 1);
        rs[2]  = __shfl_sync(0xFFFFFFFFu, v2, aL);
        rd0[2] = __shfl_sync(0xFFFFFFFFu, v2, 8 + b0);
        rd1[2] = __shfl_sync(0xFFFFFFFFu, v2, 8 + b0 + 1);
        rs[3]  = __shfl_sync(0xFFFFFFFFu, v2, 16 + aL);
        rd0[3] = __shfl_sync(0xFFFFFFFFu, v2, 24 + b0);
        rd1[3] = __shfl_sync(0xFFFFFFFFu, v2, 24 + b0 + 1);
        #pragma unroll
        for (int k = 0; k < 4; k++) {
            int gs = graph_of(src[k]), gd = graph_of(dst[k]);
            int slot = gd - g0;
            int row = (gs << 3) + aL;
            float v0 = rs[k] * rd0[k], vv1 = rs[k] * rd1[k];
            if (slot >= 0 && slot < 2) {
                atomicAdd(&acc[slot * 2048 + row * 8 + b0],     v0);
                atomicAdd(&acc[slot * 2048 + row * 8 + b0 + 1], vv1);
            } else {
                atomicAdd(out + row * 256 + (gd << 3) + b0,     v0);
                atomicAdd(out + row * 256 + (gd << 3) + b0 + 1, vv1);
            }
        }
    }
    __syncthreads();
    for (int idx = tid; idx < 4096; idx += 256) {
        float s = acc[idx];
        int slot = idx >> 11, rest = idx & 2047, row = rest >> 3, bc = rest & 7;
        int gg = g0 + slot;
        if (gg < NB && s != 0.0f)
            atomicAdd(out + row * 256 + (gg << 3) + bc, s);
    }
}

// ---------------------------------------------------------------- launch
extern "C" void kernel_launch(void* const* d_in, const int* in_sizes, int n_in,
                              void* d_out, int out_size) {
    const float* x  = (const float*)d_in[0];
    const int*   ei = (const int*)d_in[1];
    const float* We = (const float*)d_in[3];
    const float* be = (const float*)d_in[4];
    const float* Wp = (const float*)d_in[5];
    const float* bp = (const float*)d_in[6];
    float* out = (float*)d_out;

    static int smem_set = 0;
    if (!smem_set) {
        cudaFuncSetAttribute(k_gemm_mma, cudaFuncAttributeMaxDynamicSharedMemorySize,
                             SM_WORDS * 4);
        smem_set = 1;
    }

    const int init_total = OUT_ELEMS + WELEMS + XELEMS + EE;
    k_init<<<(init_total + 511) / 512, 512>>>(out, We, Wp, x, ei);
    k_scan1<<<49, 1024>>>();
    k_scan23<<<(NN + 255) / 256, 256>>>();
    k_scatter<<<(EE / 2 + 255) / 256, 256>>>(ei);
    k_neigh<<<(NN + 7) / 8, 256>>>();
    dim3 gg(NN2 / 256, 3);
    k_gemm_mma<<<gg, 256, SM_WORDS * 4>>>(be, bp);
    k_node<<<(NN + 127) / 128, 128>>>(out);
    k_adj<<<(EE + 2047) / 2048, 256>>>(out);
}

// round 14
// speedup vs baseline: 1.9230x; 1.0157x over previous
#include <cuda_runtime.h>
#include <cuda_fp16.h>

#define NN 50000
#define NN2 50176          // 196*256 padded rows (pad stays zero)
#define EE 800000
#define INF 128
#define NB 32
#define H_OFF 65536        // h starts after adj (256*256)
#define OUT_ELEMS 98304    // 256*256 + 256*128
#define WELEMS 98304       // 384*256 weight elements

__device__ __forceinline__ int graph_of(int n) { return (n * NB) / NN; }

// ---- scratch (module globals; zero-initialized, no runtime allocation) ----
__device__ float g_Z[(size_t)NN * 384];
__device__ float g_r[NN * 8];
__device__ int   g_counts[53248];      // zero at entry (static init; k_scan1 re-zeroes)
__device__ int   g_off[NN + 1];
__device__ int   g_cursor[NN];
__device__ int   g_bsum[64];
__device__ int2  g_sorted[EE];
__device__ __half g_Ah[(size_t)NN2 * 256];   // fp16 [x | neigh]; pad rows stay 0
__device__ __half g_Bh[384 * 256];           // fp16 W^T: [n][k]

// ================= helpers =================
__device__ __forceinline__ unsigned int smem_u32(const void* p) {
    unsigned int a;
    asm("{ .reg .u64 t; cvta.to.shared.u64 t, %1; cvt.u32.u64 %0, t; }" : "=r"(a) : "l"(p));
    return a;
}
#define CP_ASYNC16(dst, src) \
    asm volatile("cp.async.ca.shared.global [%0], [%1], 16;" :: "r"(dst), "l"(src) : "memory")
#define CP_COMMIT()  asm volatile("cp.async.commit_group;" ::: "memory")
#define CP_WAIT1()   asm volatile("cp.async.wait_group 1;" ::: "memory")
#define CP_WAIT0()   asm volatile("cp.async.wait_group 0;" ::: "memory")

__device__ __forceinline__ void ldmat4(unsigned* r, unsigned addr) {
    asm volatile("ldmatrix.sync.aligned.m8n8.x4.shared.b16 {%0,%1,%2,%3}, [%4];"
                 : "=r"(r[0]), "=r"(r[1]), "=r"(r[2]), "=r"(r[3]) : "r"(addr));
}
__device__ __forceinline__ void mma16n8k16(float* d, const unsigned* a, const unsigned* b) {
    asm volatile(
        "mma.sync.aligned.m16n8k16.row.col.f32.f16.f16.f32 "
        "{%0,%1,%2,%3}, {%4,%5,%6,%7}, {%8,%9}, {%0,%1,%2,%3};"
        : "+f"(d[0]), "+f"(d[1]), "+f"(d[2]), "+f"(d[3])
        : "r"(a[0]), "r"(a[1]), "r"(a[2]), "r"(a[3]), "r"(b[0]), "r"(b[1]));
}

// ---------------------------------------------------------------- init (vectorized regions)
// tasks: [0, 24576)              zero out as float4
//        [24576, 24576+98304)    W -> fp16 (scalar, transposed write)
//        [+,  +800000)           x -> fp16, 8 cols/task (float4 x2 -> uint4)
//        [+,  +200000)           hist, 4 edges/task (int4)
#define T_OUT   24576
#define T_W     98304
#define T_X     800000
#define T_HIST  200000
#define T_TOTAL (T_OUT + T_W + T_X + T_HIST)
__global__ void k_init(float* __restrict__ out,
                       const float* __restrict__ We, const float* __restrict__ Wp,
                       const float* __restrict__ x, const int* __restrict__ ei) {
    int i = blockIdx.x * blockDim.x + threadIdx.x;
    if (i < T_OUT) {
        reinterpret_cast<float4*>(out)[i] = make_float4(0.f, 0.f, 0.f, 0.f);
    } else if (i < T_OUT + T_W) {
        int idx = i - T_OUT;
        int k = idx & 255, n = idx >> 8;
        float v = (n < 128) ? We[k * 128 + n] : Wp[k * 256 + (n - 128)];
        g_Bh[n * 256 + k] = __float2half_rn(v);
    } else if (i < T_OUT + T_W + T_X) {
        int idx = i - T_OUT - T_W;          // 0..799999
        int row = idx >> 4, cg = idx & 15;  // 8 cols per task
        const float* xp = x + (size_t)row * 128 + cg * 8;
        float4 v0 = *reinterpret_cast<const float4*>(xp);
        float4 v1 = *reinterpret_cast<const float4*>(xp + 4);
        __half2 h0 = __floats2half2_rn(v0.x, v0.y);
        __half2 h1 = __floats2half2_rn(v0.z, v0.w);
        __half2 h2 = __floats2half2_rn(v1.x, v1.y);
        __half2 h3 = __floats2half2_rn(v1.z, v1.w);
        uint4 o;
        o.x = *reinterpret_cast<unsigned*>(&h0);
        o.y = *reinterpret_cast<unsigned*>(&h1);
        o.z = *reinterpret_cast<unsigned*>(&h2);
        o.w = *reinterpret_cast<unsigned*>(&h3);
        *reinterpret_cast<uint4*>(g_Ah + (size_t)row * 256 + cg * 8) = o;
    } else if (i < T_TOTAL) {
        int e = (i - T_OUT - T_W - T_X) * 4;
        int4 dv = *reinterpret_cast<const int4*>(ei + EE + e);
        atomicAdd(&g_counts[dv.x], 1);
        atomicAdd(&g_counts[dv.y], 1);
        atomicAdd(&g_counts[dv.z], 1);
        atomicAdd(&g_counts[dv.w], 1);
    }
}

// ---------------------------------------------------------------- scan stage 1
__global__ void k_scan1() {
    int tid = threadIdx.x, lane = tid & 31, wid = tid >> 5;
    int idx = blockIdx.x * 1024 + tid;
    int v = (idx < NN) ? g_counts[idx] : 0;
    if (idx < NN) g_counts[idx] = 0;
    int s = v;
    #pragma unroll
    for (int o = 1; o < 32; o <<= 1) {
        int u = __shfl_up_sync(0xFFFFFFFFu, s, o);
        if (lane >= o) s += u;
    }
    __shared__ int ws[32];
    if (lane == 31) ws[wid] = s;
    __syncthreads();
    if (wid == 0) {
        int u = ws[lane];
        #pragma unroll
        for (int o = 1; o < 32; o <<= 1) {
            int q = __shfl_up_sync(0xFFFFFFFFu, u, o);
            if (lane >= o) u += q;
        }
        ws[lane] = u;
    }
    __syncthreads();
    int excl = s - v + (wid ? ws[wid - 1] : 0);
    if (idx < NN) g_off[idx] = excl;
    if (tid == 1023) g_bsum[blockIdx.x] = excl + v;
}

// ---------------------------------------------------------------- scan stages 2+3 merged
__global__ void k_scan23() {
    __shared__ int bo[64];
    __shared__ int w0s;
    int tid = threadIdx.x;
    int v = 0, s = 0;
    if (tid < 64) {
        v = (tid < 49) ? g_bsum[tid] : 0;
        s = v;
        #pragma unroll
        for (int o = 1; o < 32; o <<= 1) {
            int u = __shfl_up_sync(0xFFFFFFFFu, s, o);
            if ((tid & 31) >= o) s += u;
        }
        if (tid == 31) w0s = s;
    }
    __syncthreads();
    if (tid < 64) bo[tid] = s - v + ((tid >= 32) ? w0s : 0);
    __syncthreads();
    int idx = blockIdx.x * 256 + tid;
    if (idx < NN) {
        int val = g_off[idx] + bo[idx >> 10];
        g_off[idx] = val;
        g_cursor[idx] = val;
    }
    if (idx == 0) g_off[NN] = EE;
}

// ---------------------------------------------------------------- scatter: 4 edges per thread
__global__ void k_scatter(const int* __restrict__ ei) {
    int e = (blockIdx.x * 256 + threadIdx.x) * 4;
    if (e < EE) {
        int4 sv = *reinterpret_cast<const int4*>(ei + e);
        int4 dv = *reinterpret_cast<const int4*>(ei + EE + e);
        int p0 = atomicAdd(&g_cursor[dv.x], 1);
        int p1 = atomicAdd(&g_cursor[dv.y], 1);
        int p2 = atomicAdd(&g_cursor[dv.z], 1);
        int p3 = atomicAdd(&g_cursor[dv.w], 1);
        g_sorted[p0] = make_int2(sv.x, dv.x);
        g_sorted[p1] = make_int2(sv.y, dv.y);
        g_sorted[p2] = make_int2(sv.z, dv.z);
        g_sorted[p3] = make_int2(sv.w, dv.w);
    }
}

// ---------------------------------------------------------------- mean aggregation (fp16 reads, MLP 8)
__global__ void k_neigh() {
    int node = blockIdx.x * 8 + (threadIdx.x >> 5);
    if (node >= NN) return;
    int lane = threadIdx.x & 31;
    int b = g_off[node], e = g_off[node + 1];
    float2 aa[8], bb[8];
    #pragma unroll
    for (int i = 0; i < 8; i++) { aa[i] = make_float2(0.f, 0.f); bb[i] = make_float2(0.f, 0.f); }
    int j = b;
    for (; j + 7 < e; j += 8) {
        uint2 u[8];
        #pragma unroll
        for (int i = 0; i < 8; i++) {
            int s0 = g_sorted[j + i].x;
            u[i] = *reinterpret_cast<const uint2*>(g_Ah + (size_t)s0 * 256 + lane * 4);
        }
        #pragma unroll
        for (int i = 0; i < 8; i++) {
            float2 f0 = __half22float2(*reinterpret_cast<__half2*>(&u[i].x));
            float2 f1 = __half22float2(*reinterpret_cast<__half2*>(&u[i].y));
            aa[i].x += f0.x; aa[i].y += f0.y;
            bb[i].x += f1.x; bb[i].y += f1.y;
        }
    }
    for (; j < e; j++) {
        int s0 = g_sorted[j].x;
        uint2 u0 = *reinterpret_cast<const uint2*>(g_Ah + (size_t)s0 * 256 + lane * 4);
        float2 f0 = __half22float2(*reinterpret_cast<__half2*>(&u0.x));
        float2 f1 = __half22float2(*reinterpret_cast<__half2*>(&u0.y));
        aa[0].x += f0.x; aa[0].y += f0.y;
        bb[0].x += f1.x; bb[0].y += f1.y;
    }
    float2 sa = make_float2(0.f, 0.f), sb = make_float2(0.f, 0.f);
    #pragma unroll
    for (int i = 0; i < 8; i++) {
        sa.x += aa[i].x; sa.y += aa[i].y;
        sb.x += bb[i].x; sb.y += bb[i].y;
    }
    float inv = 1.0f / (float)max(e - b, 1);
    __half2 h0 = __floats2half2_rn(sa.x * inv, sa.y * inv);
    __half2 h1 = __floats2half2_rn(sb.x * inv, sb.y * inv);
    uint2 o;
    o.x = *reinterpret_cast<unsigned*>(&h0);
    o.y = *reinterpret_cast<unsigned*>(&h1);
    *reinterpret_cast<uint2*>(g_Ah + (size_t)node * 256 + 128 + lane * 4) = o;
}

// ---------------------------------------------------------------- GEMM v4: fp16 m16n8k16 + ldmatrix
// CTA 256x128, K=256 in 8 chunks of 32 halves, 3-stage cp.async. SMEM 72KB.
#define SM_WORDS 18432
__global__ __launch_bounds__(256, 1) void k_gemm_mma(const float* __restrict__ be,
                                                     const float* __restrict__ bp) {
    extern __shared__ unsigned int sm[];
    int tid = threadIdx.x, lane = tid & 31, wid = tid >> 5;
    int warp_m = wid >> 1, warp_n = wid & 1;       // 4 x 2 warps, warp tile 64x64
    int g = lane >> 2, t = lane & 3;
    int m0 = blockIdx.x * 256, bt = blockIdx.y;
    unsigned int sbase = smem_u32(sm);

    float acc[4][8][4];
    #pragma unroll
    for (int mt = 0; mt < 4; mt++)
        #pragma unroll
        for (int nt = 0; nt < 8; nt++)
            #pragma unroll
            for (int j = 0; j < 4; j++) acc[mt][nt][j] = 0.0f;

    auto load_chunk = [&](int c, int s) {
        unsigned int sa = sbase + s * 16384;
        unsigned int sb = sbase + 49152 + s * 8192;
        #pragma unroll
        for (int i = 0; i < 4; i++) {
            int e = tid + i * 256;
            int row = e >> 2, ch = e & 3;
            unsigned int soff = row * 64 + ((ch ^ ((row >> 1) & 3)) << 4);
            CP_ASYNC16(sa + soff, g_Ah + (size_t)(m0 + row) * 256 + c * 32 + ch * 8);
        }
        #pragma unroll
        for (int i = 0; i < 2; i++) {
            int e = tid + i * 256;
            int n = e >> 2, ch = e & 3;
            unsigned int soff = n * 64 + ((ch ^ ((n >> 1) & 3)) << 4);
            CP_ASYNC16(sb + soff, g_Bh + (size_t)(bt * 128 + n) * 256 + c * 32 + ch * 8);
        }
    };
    auto compute = [&](int s) {
        unsigned int Ab = sbase + s * 16384;
        unsigned int Bb = sbase + 49152 + s * 8192;
        #pragma unroll
        for (int ks = 0; ks < 2; ks++) {
            unsigned a[4][4], b[4][4];
            #pragma unroll
            for (int mt = 0; mt < 4; mt++) {
                int row = warp_m * 64 + mt * 16 + ((lane >> 3) & 1) * 8 + (lane & 7);
                int ch = 2 * ks + (lane >> 4);
                ldmat4(a[mt], Ab + row * 64 + ((ch ^ ((row >> 1) & 3)) << 4));
            }
            #pragma unroll
            for (int np = 0; np < 4; np++) {
                int n = warp_n * 64 + np * 16 + ((lane >> 4) << 3) + (lane & 7);
                int ch = 2 * ks + ((lane >> 3) & 1);
                ldmat4(b[np], Bb + n * 64 + ((ch ^ ((n >> 1) & 3)) << 4));
            }
            #pragma unroll
            for (int mt = 0; mt < 4; mt++)
                #pragma unroll
                for (int np = 0; np < 4; np++) {
                    mma16n8k16(acc[mt][2 * np],     a[mt], b[np]);
                    mma16n8k16(acc[mt][2 * np + 1], a[mt], b[np] + 2);
                }
        }
    };

    load_chunk(0, 0); CP_COMMIT();
    load_chunk(1, 1); CP_COMMIT();
    #pragma unroll
    for (int c = 0; c < 8; c++) {
        if (c < 7) { CP_WAIT1(); } else { CP_WAIT0(); }
        __syncthreads();
        compute(c % 3);
        if (c + 2 < 8) { load_chunk(c + 2, (c + 2) % 3); CP_COMMIT(); }
    }

    // ---- epilogue: bias + store ----
    __syncthreads();
    float* bsh = reinterpret_cast<float*>(sm);
    const float* bias = (bt == 0) ? be : bp + (bt - 1) * 128;
    if (tid < 128) bsh[tid] = bias[tid];
    __syncthreads();
    #pragma unroll
    for (int mt = 0; mt < 4; mt++) {
        int r0 = m0 + warp_m * 64 + mt * 16 + g;
        #pragma unroll
        for (int nt = 0; nt < 8; nt++) {
            int cloc = warp_n * 64 + nt * 8 + 2 * t;
            float bx = bsh[cloc], by = bsh[cloc + 1];
            if (r0 < NN) {
                float2 v = make_float2(acc[mt][nt][0] + bx, acc[mt][nt][1] + by);
                *reinterpret_cast<float2*>(g_Z + (size_t)r0 * 384 + bt * 128 + cloc) = v;
            }
            if (r0 + 8 < NN) {
                float2 v = make_float2(acc[mt][nt][2] + bx, acc[mt][nt][3] + by);
                *reinterpret_cast<float2*>(g_Z + (size_t)(r0 + 8) * 384 + bt * 128 + cloc) = v;
            }
        }
    }
}

// ---------------------------------------------------------------- per-node: softmax -> r, accumulate h (prefetched)
__global__ __launch_bounds__(128) void k_node(float* __restrict__ out) {
    __shared__ float acc[4][2048];
    int tid = threadIdx.x, warp = tid >> 5, lane = tid & 31;
    int n0 = blockIdx.x * 128;
    int g0 = graph_of(n0);
    for (int i = tid; i < 4 * 2048; i += 128) (&acc[0][0])[i] = 0.0f;
    __syncthreads();
    float* ac = acc[warp];

    int nfirst = n0 + warp * 32;
    float4 q0, q1, ev;
    if (nfirst < NN) {
        const float* zr = g_Z + (size_t)nfirst * 384;
        q0 = *reinterpret_cast<const float4*>(zr + 128 + lane * 8);
        q1 = *reinterpret_cast<const float4*>(zr + 128 + lane * 8 + 4);
        ev = *reinterpret_cast<const float4*>(zr + lane * 4);
    }
    for (int it = 0; it < 32; it++) {
        int n = nfirst + it;
        if (n >= NN) break;
        float4 c0 = q0, c1 = q1, cev = ev;
        if (it < 31 && n + 1 < NN) {            // prefetch next row
            const float* zr = g_Z + (size_t)(n + 1) * 384;
            q0 = *reinterpret_cast<const float4*>(zr + 128 + lane * 8);
            q1 = *reinterpret_cast<const float4*>(zr + 128 + lane * 8 + 4);
            ev = *reinterpret_cast<const float4*>(zr + lane * 4);
        }
        float l[8];
        l[0] = c0.x; l[1] = c0.y; l[2] = c0.z; l[3] = c0.w;
        l[4] = c1.x; l[5] = c1.y; l[6] = c1.z; l[7] = c1.w;
        float mx = l[0];
        #pragma unroll
        for (int j = 1; j < 8; j++) mx = fmaxf(mx, l[j]);
        #pragma unroll
        for (int o = 16; o > 0; o >>= 1) mx = fmaxf(mx, __shfl_xor_sync(0xFFFFFFFFu, mx, o));
        float ex[8], s = 0.0f;
        #pragma unroll
        for (int j = 0; j < 8; j++) { ex[j] = expf(l[j] - mx); s += ex[j]; }
        #pragma unroll
        for (int o = 16; o > 0; o >>= 1) s += __shfl_xor_sync(0xFFFFFFFFu, s, o);
        float inv_s = 1.0f / s;
        float p[8], pm = -1e30f;
        #pragma unroll
        for (int j = 0; j < 8; j++) { p[j] = ex[j] * inv_s; pm = fmaxf(pm, p[j]); }
        float e2[8], se2 = 0.0f;
        #pragma unroll
        for (int j = 0; j < 8; j++) { e2[j] = expf(p[j] - pm); se2 += e2[j]; }
        float Zf = se2 + 248.0f * expf(-pm);
        float invZ = 1.0f / Zf;
        float invd = 1.0f / (se2 * invZ + 1e-13f);
        float r[8];
        #pragma unroll
        for (int j = 0; j < 8; j++) r[j] = e2[j] * invZ * invd;

        int gn = graph_of(n);
        if (lane == gn) {
            #pragma unroll
            for (int j = 0; j < 8; j++) g_r[n * 8 + j] = r[j];
        }
        float rb[8];
        #pragma unroll
        for (int j = 0; j < 8; j++) rb[j] = __shfl_sync(0xFFFFFFFFu, r[j], gn);

        int slot = gn - g0;
        float4* a4 = reinterpret_cast<float4*>(ac + slot * 1024) + lane;
        #pragma unroll
        for (int a = 0; a < 8; a++) {
            float ra = rb[a];
            float4 t = a4[a * 32];
            t.x = fmaf(ra, cev.x, t.x);
            t.y = fmaf(ra, cev.y, t.y);
            t.z = fmaf(ra, cev.z, t.z);
            t.w = fmaf(ra, cev.w, t.w);
            a4[a * 32] = t;
        }
    }
    __syncthreads();
    for (int idx = tid; idx < 2048; idx += 128) {
        float s = acc[0][idx] + acc[1][idx] + acc[2][idx] + acc[3][idx];
        int slot = idx >> 10, rest = idx & 1023, a = rest >> 7, c = rest & 127;
        int gg = g0 + slot;
        if (gg < NB && s != 0.0f)
            atomicAdd(out + H_OFF + ((gg << 3) + a) * 128 + c, s);
    }
}

// ---------------------------------------------------------------- per-edge adj: 4 edges per warp-iter
__global__ __launch_bounds__(256) void k_adj(float* __restrict__ out) {
    __shared__ float acc[2 * 2048];
    int tid = threadIdx.x;
    for (int i = tid; i < 4096; i += 256) acc[i] = 0.0f;
    __syncthreads();
    int e0 = blockIdx.x * 2048;
    int g0 = graph_of(g_sorted[e0].y);
    int warp = tid >> 5, lane = tid & 31;
    int aL = lane >> 2;
    int b0 = (lane & 3) * 2;
    int sel = lane >> 3;          // 0..3
    int li = lane & 7;

    for (int i = 0; i < 64; i++) {
        int e = e0 + warp * 256 + i * 4;
        if (e >= EE) break;
        int4 p0 = *reinterpret_cast<const int4*>(&g_sorted[e]);      // edges e, e+1
        int4 p1 = *reinterpret_cast<const int4*>(&g_sorted[e + 2]);  // edges e+2, e+3
        int idx1 = (sel == 0) ? p0.x : (sel == 1) ? p0.y : (sel == 2) ? p0.z : p0.w;
        int idx2 = (sel == 0) ? p1.x : (sel == 1) ? p1.y : (sel == 2) ? p1.z : p1.w;
        float v1 = g_r[idx1 * 8 + li];
        float v2 = g_r[idx2 * 8 + li];
        int src[4] = {p0.x, p0.z, p1.x, p1.z};
        int dst[4] = {p0.y, p0.w, p1.y, p1.w};
        float rs[4], rd0[4], rd1[4];
        rs[0]  = __shfl_sync(0xFFFFFFFFu, v1, aL);
        rd0[0] = __shfl_sync(0xFFFFFFFFu, v1, 8 + b0);
        rd1[0] = __shfl_sync(0xFFFFFFFFu, v1, 8 + b0 + 1);
        rs[1]  = __shfl_sync(0xFFFFFFFFu, v1, 16 + aL);
        rd0[1] = __shfl_sync(0xFFFFFFFFu, v1, 24 + b0);
        rd1[1] = __shfl_sync(0xFFFFFFFFu, v1, 24 + b0 + 1);
        rs[2]  = __shfl_sync(0xFFFFFFFFu, v2, aL);
        rd0[2] = __shfl_sync(0xFFFFFFFFu, v2, 8 + b0);
        rd1[2] = __shfl_sync(0xFFFFFFFFu, v2, 8 + b0 + 1);
        rs[3]  = __shfl_sync(0xFFFFFFFFu, v2, 16 + aL);
        rd0[3] = __shfl_sync(0xFFFFFFFFu, v2, 24 + b0);
        rd1[3] = __shfl_sync(0xFFFFFFFFu, v2, 24 + b0 + 1);
        #pragma unroll
        for (int k = 0; k < 4; k++) {
            int gs = graph_of(src[k]), gd = graph_of(dst[k]);
            int slot = gd - g0;
            int row = (gs << 3) + aL;
            float v0 = rs[k] * rd0[k], vv1 = rs[k] * rd1[k];
            if (slot >= 0 && slot < 2) {
                atomicAdd(&acc[slot * 2048 + row * 8 + b0],     v0);
                atomicAdd(&acc[slot * 2048 + row * 8 + b0 + 1], vv1);
            } else {
                atomicAdd(out + row * 256 + (gd << 3) + b0,     v0);
                atomicAdd(out + row * 256 + (gd << 3) + b0 + 1, vv1);
            }
        }
    }
    __syncthreads();
    for (int idx = tid; idx < 4096; idx += 256) {
        float s = acc[idx];
        int slot = idx >> 11, rest = idx & 2047, row = rest >> 3, bc = rest & 7;
        int gg = g0 + slot;
        if (gg < NB && s != 0.0f)
            atomicAdd(out + row * 256 + (gg << 3) + bc, s);
    }
}

// ---------------------------------------------------------------- launch
extern "C" void kernel_launch(void* const* d_in, const int* in_sizes, int n_in,
                              void* d_out, int out_size) {
    const float* x  = (const float*)d_in[0];
    const int*   ei = (const int*)d_in[1];
    const float* We = (const float*)d_in[3];
    const float* be = (const float*)d_in[4];
    const float* Wp = (const float*)d_in[5];
    const float* bp = (const float*)d_in[6];
    float* out = (float*)d_out;

    static int smem_set = 0;
    if (!smem_set) {
        cudaFuncSetAttribute(k_gemm_mma, cudaFuncAttributeMaxDynamicSharedMemorySize,
                             SM_WORDS * 4);
        smem_set = 1;
    }

    k_init<<<(T_TOTAL + 511) / 512, 512>>>(out, We, Wp, x, ei);
    k_scan1<<<49, 1024>>>();
    k_scan23<<<(NN + 255) / 256, 256>>>();
    k_scatter<<<(EE / 4 + 255) / 256, 256>>>(ei);
    k_neigh<<<(NN + 7) / 8, 256>>>();
    dim3 gg(NN2 / 256, 3);
    k_gemm_mma<<<gg, 256, SM_WORDS * 4>>>(be, bp);
    k_node<<<(NN + 127) / 128, 128>>>(out);
    k_adj<<<(EE + 2047) / 2048, 256>>>(out);
}